// round 13
// baseline (speedup 1.0000x reference)
#include <cuda_runtime.h>
#include <cuda_bf16.h>
#include <cstdint>

#define T_STEPS 8
#define BATCH   128
#define NIMG    (T_STEPS * BATCH)   // 1024

// ======================= helpers =======================
__device__ __forceinline__ uint32_t smem_u32(const void* p) {
    uint32_t a;
    asm("{ .reg .u64 t; cvta.to.shared.u64 t, %1; cvt.u32.u64 %0, t; }" : "=r"(a) : "l"(p));
    return a;
}
#define SWZ(off) ((off) ^ (((off) >> 3) & 0x70))

#define MMA_BF16(acc, a, b0, b1) \
    asm volatile("mma.sync.aligned.m16n8k16.row.col.f32.bf16.bf16.f32 " \
        "{%0,%1,%2,%3}, {%4,%5,%6,%7}, {%8,%9}, {%0,%1,%2,%3};" \
        : "+f"((acc)[0]), "+f"((acc)[1]), "+f"((acc)[2]), "+f"((acc)[3]) \
        : "r"((a)[0]), "r"((a)[1]), "r"((a)[2]), "r"((a)[3]), "r"(b0), "r"(b1))

#define LDMATRIX_X4(a, addr) \
    asm volatile("ldmatrix.sync.aligned.m8n8.x4.shared.b16 {%0,%1,%2,%3}, [%4];" \
        : "=r"((a)[0]), "=r"((a)[1]), "=r"((a)[2]), "=r"((a)[3]) : "r"(addr))

// ======================= scratch =======================
__device__ __align__(16) float         g_pre1[NIMG * 1024 * 64];          // conv1 out [n][px][64c]
__device__ __align__(16) __nv_bfloat16 g_s1  [NIMG * 1024 * 64];          // spikes bf16
__device__ __align__(16) float         g_pre2[(size_t)NIMG * 1024 * 128]; // conv2 out [n][px][128c]
__device__ __align__(16) __nv_bfloat16 g_s2  [NIMG * 256 * 128];          // pooled spikes bf16
__device__ __align__(16) float         g_pre3[NIMG * 256 * 256];          // conv3 out [n][px][256c]
__device__ __align__(16) float         g_s3  [NIMG * 16384];              // fc input fp32 [n][c*64+h*8+w]
__device__ __align__(16) __nv_bfloat16 g_w2s [3 * 9 * 128 * 64];          // [s][kk][co][cin]
__device__ __align__(16) __nv_bfloat16 g_w3s [3 * 9 * 2 * 2 * 128 * 64];  // [s][kk][cc][nt][co][cin]
__device__ float g_fc  [NIMG * 512];
__device__ float g_feat[BATCH * 512];

// smem layout (bytes): BN at 16 (3*512), A slab at 2048 (16KB, SW128),
// B slabs at 18432 (3 x 18432, rows padded to 144B)
#define SM_BN    16
#define SM_A     2048
#define SM_B     18432
#define SM_BSLAB 18432
#define SMEM_BYTES 73728

// ======================= weight splitting (exact 8+8+8) =======================
__device__ __forceinline__ void split3(float w, __nv_bfloat16& h, __nv_bfloat16& m, __nv_bfloat16& l)
{
    h = __float2bfloat16_rz(w);
    float r1 = w - __bfloat162float(h);
    m = __float2bfloat16_rz(r1);
    float r2 = r1 - __bfloat162float(m);
    l = __float2bfloat16_rz(r2);
}

__global__ void wprep2(const float* __restrict__ w2)
{
    int i = blockIdx.x * 256 + threadIdx.x;          // 128*64*9 = 73728
    if (i >= 128 * 64 * 9) return;
    int co = i / 576, r = i % 576, cin = r / 9, kk = r % 9;
    __nv_bfloat16 h, m, l;
    split3(w2[co * 576 + cin * 9 + kk], h, m, l);
    int base = kk * 8192 + co * 64 + cin;
    g_w2s[base] = h; g_w2s[9 * 8192 + base] = m; g_w2s[18 * 8192 + base] = l;
}

__global__ void wprep3(const float* __restrict__ w3)
{
    int i = blockIdx.x * 256 + threadIdx.x;          // 256*128*9 = 294912
    if (i >= 256 * 128 * 9) return;
    int co = i / 1152, r = i % 1152, cin = r / 9, kk = r % 9;
    __nv_bfloat16 h, m, l;
    split3(w3[co * 1152 + cin * 9 + kk], h, m, l);
    int nt = co >> 7, col = co & 127, cc = cin >> 6, cinl = cin & 63;
    int idx = ((((kk * 2 + cc) * 2 + nt) * 128 + col) * 64 + cinl);
    g_w3s[idx] = h;
    g_w3s[294912 + idx] = m;
    g_w3s[2 * 294912 + idx] = l;
}

// ======================= conv1: 3->64, scalar, out [n][px][c] =======================
__global__ void __launch_bounds__(256) conv1_bn(
    const float* __restrict__ x, const float* __restrict__ w,
    const float* __restrict__ g, const float* __restrict__ bb,
    const float* __restrict__ mm, const float* __restrict__ vv)
{
    const int n   = blockIdx.z;
    const int co0 = blockIdx.y * 8;
    const int pix = blockIdx.x * 256 + threadIdx.x;
    const int h = pix >> 5, wi = pix & 31;

    __shared__ float ws[8 * 27];
    if (threadIdx.x < 216) ws[threadIdx.x] = w[co0 * 27 + threadIdx.x];
    __syncthreads();

    const float* xb = x + n * 3 * 1024;
    float acc[8];
#pragma unroll
    for (int j = 0; j < 8; j++) acc[j] = 0.f;

#pragma unroll
    for (int c = 0; c < 3; c++)
#pragma unroll
        for (int ky = 0; ky < 3; ky++)
#pragma unroll
            for (int kx = 0; kx < 3; kx++) {
                int ih = h + ky - 1, iw = wi + kx - 1;
                float v = 0.f;
                if ((unsigned)ih < 32u && (unsigned)iw < 32u)
                    v = __ldg(&xb[c * 1024 + ih * 32 + iw]);
                int k = c * 9 + ky * 3 + kx;
#pragma unroll
                for (int j = 0; j < 8; j++)
                    acc[j] = fmaf(v, ws[j * 27 + k], acc[j]);
            }

#pragma unroll
    for (int j = 0; j < 8; j++) {
        int c = co0 + j;
        float scale = g[c] * rsqrtf(vv[c] + 1e-5f);
        g_pre1[((size_t)n * 1024 + pix) * 64 + c] = (acc[j] - mm[c]) * scale + bb[c];
    }
}

// ======================= lif1: pre1 -> bf16 spikes =======================
__global__ void lif1_kernel()
{
    const size_t i = (size_t)blockIdx.x * 256 + threadIdx.x;   // B*1024*64
    const size_t stride = (size_t)BATCH * 1024 * 64;
    float v = 0.f;
#pragma unroll
    for (int t = 0; t < T_STEPS; t++) {
        float xv = g_pre1[t * stride + i];
        v = v + (xv - v) * 0.5f;
        float s = (v >= 1.0f) ? 1.0f : 0.0f;
        g_s1[t * stride + i] = __float2bfloat16(s);
        v = v * (1.0f - s);
    }
}

// ======================= conv2: 64->128, HMMA implicit GEMM =======================
// grid (8 m-tiles, 1024 imgs), block 256 (8 warps = 2m x 4n).
__global__ void __launch_bounds__(256, 2) conv2_hmma(
    const float* __restrict__ g, const float* __restrict__ bb,
    const float* __restrict__ mm, const float* __restrict__ vv)
{
    extern __shared__ char smem[];
    const int n     = blockIdx.y;
    const int mbase = blockIdx.x * 128;
    const int tid   = threadIdx.x;
    const int lane  = tid & 31, warp = tid >> 5;
    const int wm = warp >> 2, wn = warp & 3;
    const uint32_t smb = smem_u32(smem);

    float* s_scl = (float*)(smem + SM_BN);
    float* s_nm  = (float*)(smem + SM_BN + 512);
    float* s_bi  = (float*)(smem + SM_BN + 1024);
    if (tid < 128) {
        float sc = g[tid] * rsqrtf(vv[tid] + 1e-5f);
        s_scl[tid] = sc; s_nm[tid] = -mm[tid]; s_bi[tid] = bb[tid];
    }

    float acc[4][4][4];
#pragma unroll
    for (int a = 0; a < 4; a++)
#pragma unroll
        for (int b = 0; b < 4; b++)
#pragma unroll
            for (int c = 0; c < 4; c++) acc[a][b][c] = 0.f;

    const int row = tid >> 1, half = tid & 1;
    const uint4 z4 = make_uint4(0, 0, 0, 0);

#pragma unroll 1
    for (int kk = 0; kk < 9; kk++) {
        const int ky = kk / 3 - 1, kx = kk % 3 - 1;
        __syncthreads();
        // A slab: 128 px x 64 cin bf16, SW128 swizzle, zero-padded at borders
        {
            int px = mbase + row;
            int h = (px >> 5) + ky, w = (px & 31) + kx;
            bool ok = (unsigned)h < 32u && (unsigned)w < 32u;
            const uint4* src = (const uint4*)(g_s1 + ((size_t)(n * 1024 + h * 32 + w) * 64 + half * 32));
#pragma unroll
            for (int j = 0; j < 4; j++) {
                uint4 v = ok ? __ldg(src + j) : z4;
                *(uint4*)(smem + SM_A + SWZ(row * 128 + half * 64 + j * 16)) = v;
            }
        }
        // B slabs: 3 splits x 128 co x 64 cin, rows padded to 144B
#pragma unroll 1
        for (int it = tid; it < 3 * 128 * 8; it += 256) {
            int s = it >> 10, r = it & 1023, co = r >> 3, q = r & 7;
            const uint4* src = (const uint4*)(g_w2s + ((size_t)(s * 9 + kk) * 128 + co) * 64 + q * 8);
            *(uint4*)(smem + SM_B + s * SM_BSLAB + co * 144 + q * 16) = __ldg(src);
        }
        __syncthreads();

#pragma unroll
        for (int ks = 0; ks < 4; ks++) {
            uint32_t afr[4][4];
#pragma unroll
            for (int mi = 0; mi < 4; mi++) {
                int arow = wm * 64 + mi * 16 + (lane & 7) + ((lane >> 3) & 1) * 8;
                int acol = ks * 32 + ((lane >> 4) & 1) * 16;
                uint32_t addr = smb + SM_A + SWZ(arow * 128 + acol);
                LDMATRIX_X4(afr[mi], addr);
            }
#pragma unroll
            for (int s = 0; s < 3; s++) {
#pragma unroll
                for (int nj = 0; nj < 4; nj++) {
                    int nn = wn * 32 + nj * 8 + (lane >> 2);
                    int k0 = ks * 16 + (lane & 3) * 2;
                    const char* bp = smem + SM_B + s * SM_BSLAB + nn * 144 + k0 * 2;
                    uint32_t b0 = *(const uint32_t*)bp;
                    uint32_t b1 = *(const uint32_t*)(bp + 16);
#pragma unroll
                    for (int mi = 0; mi < 4; mi++)
                        MMA_BF16(acc[mi][nj], afr[mi], b0, b1);
                }
            }
        }
    }

    // epilogue: BN, write [n][px][128]
    float* obase = g_pre2 + (size_t)n * 1024 * 128;
#pragma unroll
    for (int mi = 0; mi < 4; mi++) {
        int px0 = mbase + wm * 64 + mi * 16 + (lane >> 2);
#pragma unroll
        for (int nj = 0; nj < 4; nj++) {
            int co = wn * 32 + nj * 8 + (lane & 3) * 2;
            float sc0 = s_scl[co], sc1 = s_scl[co + 1];
            float nm0 = s_nm[co],  nm1 = s_nm[co + 1];
            float bi0 = s_bi[co],  bi1 = s_bi[co + 1];
            float2 v0 = make_float2(fmaf(acc[mi][nj][0] + nm0, sc0, bi0),
                                    fmaf(acc[mi][nj][1] + nm1, sc1, bi1));
            float2 v1 = make_float2(fmaf(acc[mi][nj][2] + nm0, sc0, bi0),
                                    fmaf(acc[mi][nj][3] + nm1, sc1, bi1));
            *(float2*)(obase + (size_t)px0 * 128 + co)       = v0;
            *(float2*)(obase + (size_t)(px0 + 8) * 128 + co) = v1;
        }
    }
}

// ======================= conv3: 128->256, HMMA implicit GEMM =======================
// grid (4 = 2mt x 2nt, 1024 imgs), block 256. 18 chunks (kk x cinchunk).
__global__ void __launch_bounds__(256, 2) conv3_hmma(
    const float* __restrict__ g, const float* __restrict__ bb,
    const float* __restrict__ mm, const float* __restrict__ vv)
{
    extern __shared__ char smem[];
    const int n  = blockIdx.y;
    const int mt = blockIdx.x >> 1, nt = blockIdx.x & 1;
    const int tid  = threadIdx.x;
    const int lane = tid & 31, warp = tid >> 5;
    const int wm = warp >> 2, wn = warp & 3;
    const uint32_t smb = smem_u32(smem);

    float* s_scl = (float*)(smem + SM_BN);
    float* s_nm  = (float*)(smem + SM_BN + 512);
    float* s_bi  = (float*)(smem + SM_BN + 1024);
    if (tid < 128) {
        int c = nt * 128 + tid;
        float sc = g[c] * rsqrtf(vv[c] + 1e-5f);
        s_scl[tid] = sc; s_nm[tid] = -mm[c]; s_bi[tid] = bb[c];
    }

    float acc[4][4][4];
#pragma unroll
    for (int a = 0; a < 4; a++)
#pragma unroll
        for (int b = 0; b < 4; b++)
#pragma unroll
            for (int c = 0; c < 4; c++) acc[a][b][c] = 0.f;

    const int row = tid >> 1, half = tid & 1;
    const uint4 z4 = make_uint4(0, 0, 0, 0);

#pragma unroll 1
    for (int ch = 0; ch < 18; ch++) {
        const int kk = ch >> 1, cc = ch & 1;
        const int ky = kk / 3 - 1, kx = kk % 3 - 1;
        __syncthreads();
        // A slab from g_s2 [n][256px][128cin], take cin chunk cc
        {
            int px = mt * 128 + row;
            int h = (px >> 4) + ky, w = (px & 15) + kx;
            bool ok = (unsigned)h < 16u && (unsigned)w < 16u;
            const uint4* src = (const uint4*)(g_s2 + ((size_t)(n * 256 + h * 16 + w) * 128 + cc * 64 + half * 32));
#pragma unroll
            for (int j = 0; j < 4; j++) {
                uint4 v = ok ? __ldg(src + j) : z4;
                *(uint4*)(smem + SM_A + SWZ(row * 128 + half * 64 + j * 16)) = v;
            }
        }
        // B slabs: [s][kk][cc][nt][co][cin]
#pragma unroll 1
        for (int it = tid; it < 3 * 128 * 8; it += 256) {
            int s = it >> 10, r = it & 1023, co = r >> 3, q = r & 7;
            size_t bidx = (size_t)s * 294912 + ((size_t)(((kk * 2 + cc) * 2 + nt) * 128 + co)) * 64 + q * 8;
            *(uint4*)(smem + SM_B + s * SM_BSLAB + co * 144 + q * 16) = __ldg((const uint4*)(g_w3s + bidx));
        }
        __syncthreads();

#pragma unroll
        for (int ks = 0; ks < 4; ks++) {
            uint32_t afr[4][4];
#pragma unroll
            for (int mi = 0; mi < 4; mi++) {
                int arow = wm * 64 + mi * 16 + (lane & 7) + ((lane >> 3) & 1) * 8;
                int acol = ks * 32 + ((lane >> 4) & 1) * 16;
                uint32_t addr = smb + SM_A + SWZ(arow * 128 + acol);
                LDMATRIX_X4(afr[mi], addr);
            }
#pragma unroll
            for (int s = 0; s < 3; s++) {
#pragma unroll
                for (int nj = 0; nj < 4; nj++) {
                    int nn = wn * 32 + nj * 8 + (lane >> 2);
                    int k0 = ks * 16 + (lane & 3) * 2;
                    const char* bp = smem + SM_B + s * SM_BSLAB + nn * 144 + k0 * 2;
                    uint32_t b0 = *(const uint32_t*)bp;
                    uint32_t b1 = *(const uint32_t*)(bp + 16);
#pragma unroll
                    for (int mi = 0; mi < 4; mi++)
                        MMA_BF16(acc[mi][nj], afr[mi], b0, b1);
                }
            }
        }
    }

    // epilogue: BN, write [n][px][256] (cols nt*128..+128)
    float* obase = g_pre3 + (size_t)n * 256 * 256 + nt * 128;
#pragma unroll
    for (int mi = 0; mi < 4; mi++) {
        int px0 = mt * 128 + wm * 64 + mi * 16 + (lane >> 2);
#pragma unroll
        for (int nj = 0; nj < 4; nj++) {
            int co = wn * 32 + nj * 8 + (lane & 3) * 2;
            float sc0 = s_scl[co], sc1 = s_scl[co + 1];
            float nm0 = s_nm[co],  nm1 = s_nm[co + 1];
            float bi0 = s_bi[co],  bi1 = s_bi[co + 1];
            float2 v0 = make_float2(fmaf(acc[mi][nj][0] + nm0, sc0, bi0),
                                    fmaf(acc[mi][nj][1] + nm1, sc1, bi1));
            float2 v1 = make_float2(fmaf(acc[mi][nj][2] + nm0, sc0, bi0),
                                    fmaf(acc[mi][nj][3] + nm1, sc1, bi1));
            *(float2*)(obase + (size_t)px0 * 256 + co)       = v0;
            *(float2*)(obase + (size_t)(px0 + 8) * 256 + co) = v1;
        }
    }
}

// ======================= lif2 + pool: pre2 -> s2 bf16 =======================
__global__ void lif2_pool()
{
    const int i = blockIdx.x * 256 + threadIdx.x;   // B*16*16*128
    const int co = i & 127;
    const int wo = (i >> 7) & 15;
    const int ho = (i >> 11) & 15;
    const int b  = i >> 15;

    float v00 = 0.f, v01 = 0.f, v10 = 0.f, v11 = 0.f;
#pragma unroll
    for (int t = 0; t < T_STEPS; t++) {
        const float* p = g_pre2 + ((size_t)((t * BATCH + b) * 1024 + (2 * ho) * 32 + 2 * wo)) * 128 + co;
        float x00 = p[0], x01 = p[128], x10 = p[32 * 128], x11 = p[33 * 128];
        v00 += (x00 - v00) * 0.5f; float s00 = (v00 >= 1.f) ? 1.f : 0.f; v00 *= (1.f - s00);
        v01 += (x01 - v01) * 0.5f; float s01 = (v01 >= 1.f) ? 1.f : 0.f; v01 *= (1.f - s01);
        v10 += (x10 - v10) * 0.5f; float s10 = (v10 >= 1.f) ? 1.f : 0.f; v10 *= (1.f - s10);
        v11 += (x11 - v11) * 0.5f; float s11 = (v11 >= 1.f) ? 1.f : 0.f; v11 *= (1.f - s11);
        float s = fmaxf(fmaxf(s00, s01), fmaxf(s10, s11));
        g_s2[((size_t)(t * BATCH + b) * 256 + ho * 16 + wo) * 128 + co] = __float2bfloat16(s);
    }
}

// ======================= lif3 + pool: pre3 -> s3 fp32 (c*64+h*8+w order) =======================
__global__ void lif3_pool()
{
    const int i = blockIdx.x * 256 + threadIdx.x;   // B*8*8*256
    const int co = i & 255;
    const int wo = (i >> 8) & 7;
    const int ho = (i >> 11) & 7;
    const int b  = i >> 14;

    float v00 = 0.f, v01 = 0.f, v10 = 0.f, v11 = 0.f;
#pragma unroll
    for (int t = 0; t < T_STEPS; t++) {
        const float* p = g_pre3 + ((size_t)((t * BATCH + b) * 256 + (2 * ho) * 16 + 2 * wo)) * 256 + co;
        float x00 = p[0], x01 = p[256], x10 = p[16 * 256], x11 = p[17 * 256];
        v00 += (x00 - v00) * 0.5f; float s00 = (v00 >= 1.f) ? 1.f : 0.f; v00 *= (1.f - s00);
        v01 += (x01 - v01) * 0.5f; float s01 = (v01 >= 1.f) ? 1.f : 0.f; v01 *= (1.f - s01);
        v10 += (x10 - v10) * 0.5f; float s10 = (v10 >= 1.f) ? 1.f : 0.f; v10 *= (1.f - s10);
        v11 += (x11 - v11) * 0.5f; float s11 = (v11 >= 1.f) ? 1.f : 0.f; v11 *= (1.f - s11);
        float s = fmaxf(fmaxf(s00, s01), fmaxf(s10, s11));
        g_s3[(size_t)(t * BATCH + b) * 16384 + co * 64 + ho * 8 + wo] = s;
    }
}

// ======================= FC GEMM =======================
__global__ void __launch_bounds__(256) fc_gemm(const float* __restrict__ W)
{
    const int f0 = blockIdx.x * 64;
    const int m0 = blockIdx.y * 64;
    const int tid = threadIdx.x;
    const int tx = tid & 15, ty = tid >> 4;

    __shared__ float As[16][64];
    __shared__ float Bs[16][64];

    float acc[4][4];
#pragma unroll
    for (int i = 0; i < 4; i++)
#pragma unroll
        for (int j = 0; j < 4; j++) acc[i][j] = 0.f;

    const int lrow = tid >> 2;
    const int lk   = (tid & 3) * 4;

    for (int k0 = 0; k0 < 16384; k0 += 16) {
        float4 a = *(const float4*)(g_s3 + (size_t)(m0 + lrow) * 16384 + k0 + lk);
        float4 b = *(const float4*)(W + (size_t)(f0 + lrow) * 16384 + k0 + lk);
        As[lk + 0][lrow] = a.x; As[lk + 1][lrow] = a.y;
        As[lk + 2][lrow] = a.z; As[lk + 3][lrow] = a.w;
        Bs[lk + 0][lrow] = b.x; Bs[lk + 1][lrow] = b.y;
        Bs[lk + 2][lrow] = b.z; Bs[lk + 3][lrow] = b.w;
        __syncthreads();
#pragma unroll
        for (int kk = 0; kk < 16; kk++) {
            float4 ra = *(const float4*)&As[kk][ty * 4];
            float4 rb = *(const float4*)&Bs[kk][tx * 4];
            float av[4] = {ra.x, ra.y, ra.z, ra.w};
            float bv[4] = {rb.x, rb.y, rb.z, rb.w};
#pragma unroll
            for (int i = 0; i < 4; i++)
#pragma unroll
                for (int j = 0; j < 4; j++)
                    acc[i][j] = fmaf(av[i], bv[j], acc[i][j]);
        }
        __syncthreads();
    }

#pragma unroll
    for (int i = 0; i < 4; i++)
#pragma unroll
        for (int j = 0; j < 4; j++)
            g_fc[(m0 + ty * 4 + i) * 512 + f0 + tx * 4 + j] = acc[i][j];
}

// ======================= LIF fc + mean =======================
__global__ void lif_fc_mean()
{
    const int i = blockIdx.x * 256 + threadIdx.x;
    float v = 0.f, sum = 0.f;
#pragma unroll
    for (int t = 0; t < T_STEPS; t++) {
        float xv = g_fc[t * (BATCH * 512) + i];
        v = v + (xv - v) * 0.5f;
        float s = (v >= 1.0f) ? 1.0f : 0.0f;
        v = v * (1.0f - s);
        sum += s;
    }
    g_feat[i] = sum * 0.125f;
}

// ======================= cosine head =======================
__device__ __forceinline__ float blk_sum(float v, float* red)
{
    const int lane = threadIdx.x & 31, wp = threadIdx.x >> 5;
#pragma unroll
    for (int o = 16; o > 0; o >>= 1) v += __shfl_down_sync(0xffffffffu, v, o);
    if (lane == 0) red[wp] = v;
    __syncthreads();
    float r = (threadIdx.x < 8) ? red[threadIdx.x] : 0.f;
    if (wp == 0) {
#pragma unroll
        for (int o = 4; o > 0; o >>= 1) r += __shfl_down_sync(0xffu, r, o);
        if (lane == 0) red[0] = r;
    }
    __syncthreads();
    float res = red[0];
    __syncthreads();
    return res;
}

__global__ void final_head(const float* __restrict__ protos, float* __restrict__ out)
{
    const int b = blockIdx.x;
    const int tid = threadIdx.x;
    __shared__ float sf[512];
    __shared__ float red[8];

    for (int i = tid; i < 512; i += 256) sf[i] = g_feat[b * 512 + i];
    __syncthreads();

    float ps = 0.f;
    for (int i = tid; i < 512; i += 256) ps += sf[i] * sf[i];
    float nf = sqrtf(blk_sum(ps, red));
    nf = fmaxf(nf, 1e-12f);

    for (int p = 0; p < 10; p++) {
        float pd = 0.f, pq = 0.f;
        for (int i = tid; i < 512; i += 256) {
            float pv = __ldg(&protos[p * 512 + i]);
            pd += sf[i] * pv;
            pq += pv * pv;
        }
        pd = blk_sum(pd, red);
        pq = blk_sum(pq, red);
        if (tid == 0)
            out[b * 10 + p] = 10.f * pd / (nf * fmaxf(sqrtf(pq), 1e-12f));
    }
}

// ======================= launch =======================
extern "C" void kernel_launch(void* const* d_in, const int* in_sizes, int n_in,
                              void* d_out, int out_size)
{
    const float* x = nullptr;
    const float* w1 = nullptr; const float* w2 = nullptr; const float* w3 = nullptr;
    const float* fcw = nullptr; const float* protos = nullptr;
    const float* bn64[4]  = {nullptr, nullptr, nullptr, nullptr};
    const float* bn128[4] = {nullptr, nullptr, nullptr, nullptr};
    const float* bn256[4] = {nullptr, nullptr, nullptr, nullptr};
    int c64 = 0, c128 = 0, c256 = 0;

    for (int i = 0; i < n_in; i++) {
        const float* p = (const float*)d_in[i];
        switch (in_sizes[i]) {
            case 3145728: x = p; break;
            case 1728:    w1 = p; break;
            case 73728:   w2 = p; break;
            case 294912:  w3 = p; break;
            case 8388608: fcw = p; break;
            case 5120:    protos = p; break;
            case 64:  if (c64  < 4) bn64[c64++]   = p; break;
            case 128: if (c128 < 4) bn128[c128++] = p; break;
            case 256: if (c256 < 4) bn256[c256++] = p; break;
            default: break;
        }
    }
    if (!x || !w1 || !w2 || !w3 || !fcw || !protos) return;

    cudaFuncSetAttribute(conv2_hmma, cudaFuncAttributeMaxDynamicSharedMemorySize, SMEM_BYTES);
    cudaFuncSetAttribute(conv3_hmma, cudaFuncAttributeMaxDynamicSharedMemorySize, SMEM_BYTES);

    wprep2<<<288, 256>>>(w2);
    wprep3<<<1152, 256>>>(w3);
    conv1_bn<<<dim3(4, 8, NIMG), 256>>>(x, w1, bn64[0], bn64[1], bn64[2], bn64[3]);
    lif1_kernel<<<32768, 256>>>();
    conv2_hmma<<<dim3(8, NIMG), 256, SMEM_BYTES>>>(bn128[0], bn128[1], bn128[2], bn128[3]);
    lif2_pool<<<16384, 256>>>();
    conv3_hmma<<<dim3(4, NIMG), 256, SMEM_BYTES>>>(bn256[0], bn256[1], bn256[2], bn256[3]);
    lif3_pool<<<8192, 256>>>();
    fc_gemm<<<dim3(8, 16), 256>>>(fcw);
    lif_fc_mean<<<256, 256>>>();
    final_head<<<BATCH, 256>>>(protos, (float*)d_out);
}

// round 14
// speedup vs baseline: 1.0024x; 1.0024x over previous
#include <cuda_runtime.h>
#include <cuda_bf16.h>
#include <cstdint>

#define T_STEPS 8
#define BATCH   128
#define NIMG    (T_STEPS * BATCH)   // 1024

// ======================= helpers =======================
__device__ __forceinline__ uint32_t smem_u32(const void* p) {
    uint32_t a;
    asm("{ .reg .u64 t; cvta.to.shared.u64 t, %1; cvt.u32.u64 %0, t; }" : "=r"(a) : "l"(p));
    return a;
}
#define SWZ(off) ((off) ^ (((off) >> 3) & 0x70))

#define MMA_BF16(acc, a, b0, b1) \
    asm volatile("mma.sync.aligned.m16n8k16.row.col.f32.bf16.bf16.f32 " \
        "{%0,%1,%2,%3}, {%4,%5,%6,%7}, {%8,%9}, {%0,%1,%2,%3};" \
        : "+f"((acc)[0]), "+f"((acc)[1]), "+f"((acc)[2]), "+f"((acc)[3]) \
        : "r"((a)[0]), "r"((a)[1]), "r"((a)[2]), "r"((a)[3]), "r"(b0), "r"(b1))

#define LDMATRIX_X4(a, addr) \
    asm volatile("ldmatrix.sync.aligned.m8n8.x4.shared.b16 {%0,%1,%2,%3}, [%4];" \
        : "=r"((a)[0]), "=r"((a)[1]), "=r"((a)[2]), "=r"((a)[3]) : "r"(addr))

// ======================= scratch =======================
__device__ __align__(16) float         g_pre1[NIMG * 1024 * 64];          // conv1 out [n][px][64c]
__device__ __align__(16) __nv_bfloat16 g_s1  [NIMG * 1024 * 64];          // spikes bf16
__device__ __align__(16) float         g_pre2[(size_t)NIMG * 1024 * 128]; // conv2 out [n][px][128c]
__device__ __align__(16) __nv_bfloat16 g_s2  [NIMG * 256 * 128];          // pooled spikes bf16
__device__ __align__(16) float         g_pre3[NIMG * 256 * 256];          // conv3 out [n][px][256c]
__device__ __align__(16) float         g_s3  [NIMG * 16384];              // fc input fp32 [n][c*64+h*8+w]
__device__ __align__(16) __nv_bfloat16 g_w2s [3 * 9 * 128 * 64];          // [s][kk][co][cin]
__device__ __align__(16) __nv_bfloat16 g_w3s [3 * 9 * 2 * 2 * 128 * 64];  // [s][kk][cc][nt][co][cin]
__device__ float g_fc  [NIMG * 512];
__device__ float g_feat[BATCH * 512];

// smem layout (bytes): BN at 16 (3*512), A slab at 2048 (16KB, SW128),
// B slabs at 18432 (3 x 18432, rows padded to 144B)
#define SM_BN    16
#define SM_A     2048
#define SM_B     18432
#define SM_BSLAB 18432
#define SMEM_BYTES 73728

// ======================= weight splitting (exact 8+8+8) =======================
__device__ __forceinline__ void split3(float w, __nv_bfloat16& h, __nv_bfloat16& m, __nv_bfloat16& l)
{
    h = __float2bfloat16_rz(w);
    float r1 = w - __bfloat162float(h);
    m = __float2bfloat16_rz(r1);
    float r2 = r1 - __bfloat162float(m);
    l = __float2bfloat16_rz(r2);
}

__global__ void wprep2(const float* __restrict__ w2)
{
    int i = blockIdx.x * 256 + threadIdx.x;          // 128*64*9 = 73728
    if (i >= 128 * 64 * 9) return;
    int co = i / 576, r = i % 576, cin = r / 9, kk = r % 9;
    __nv_bfloat16 h, m, l;
    split3(w2[co * 576 + cin * 9 + kk], h, m, l);
    int base = kk * 8192 + co * 64 + cin;
    g_w2s[base] = h; g_w2s[9 * 8192 + base] = m; g_w2s[18 * 8192 + base] = l;
}

__global__ void wprep3(const float* __restrict__ w3)
{
    int i = blockIdx.x * 256 + threadIdx.x;          // 256*128*9 = 294912
    if (i >= 256 * 128 * 9) return;
    int co = i / 1152, r = i % 1152, cin = r / 9, kk = r % 9;
    __nv_bfloat16 h, m, l;
    split3(w3[co * 1152 + cin * 9 + kk], h, m, l);
    int nt = co >> 7, col = co & 127, cc = cin >> 6, cinl = cin & 63;
    int idx = ((((kk * 2 + cc) * 2 + nt) * 128 + col) * 64 + cinl);
    g_w3s[idx] = h;
    g_w3s[294912 + idx] = m;
    g_w3s[2 * 294912 + idx] = l;
}

// ======================= conv1: 3->64, scalar, out [n][px][c] =======================
__global__ void __launch_bounds__(256) conv1_bn(
    const float* __restrict__ x, const float* __restrict__ w,
    const float* __restrict__ g, const float* __restrict__ bb,
    const float* __restrict__ mm, const float* __restrict__ vv)
{
    const int n   = blockIdx.z;
    const int co0 = blockIdx.y * 8;
    const int pix = blockIdx.x * 256 + threadIdx.x;
    const int h = pix >> 5, wi = pix & 31;

    __shared__ float ws[8 * 27];
    if (threadIdx.x < 216) ws[threadIdx.x] = w[co0 * 27 + threadIdx.x];
    __syncthreads();

    const float* xb = x + n * 3 * 1024;
    float acc[8];
#pragma unroll
    for (int j = 0; j < 8; j++) acc[j] = 0.f;

#pragma unroll
    for (int c = 0; c < 3; c++)
#pragma unroll
        for (int ky = 0; ky < 3; ky++)
#pragma unroll
            for (int kx = 0; kx < 3; kx++) {
                int ih = h + ky - 1, iw = wi + kx - 1;
                float v = 0.f;
                if ((unsigned)ih < 32u && (unsigned)iw < 32u)
                    v = __ldg(&xb[c * 1024 + ih * 32 + iw]);
                int k = c * 9 + ky * 3 + kx;
#pragma unroll
                for (int j = 0; j < 8; j++)
                    acc[j] = fmaf(v, ws[j * 27 + k], acc[j]);
            }

#pragma unroll
    for (int j = 0; j < 8; j++) {
        int c = co0 + j;
        float scale = g[c] * rsqrtf(vv[c] + 1e-5f);
        g_pre1[((size_t)n * 1024 + pix) * 64 + c] = (acc[j] - mm[c]) * scale + bb[c];
    }
}

// ======================= lif1: pre1 -> bf16 spikes =======================
__global__ void lif1_kernel()
{
    const size_t i = (size_t)blockIdx.x * 256 + threadIdx.x;   // B*1024*64
    const size_t stride = (size_t)BATCH * 1024 * 64;
    float v = 0.f;
#pragma unroll
    for (int t = 0; t < T_STEPS; t++) {
        float xv = g_pre1[t * stride + i];
        v = v + (xv - v) * 0.5f;
        float s = (v >= 1.0f) ? 1.0f : 0.0f;
        g_s1[t * stride + i] = __float2bfloat16(s);
        v = v * (1.0f - s);
    }
}

// ======================= conv2: 64->128, HMMA implicit GEMM =======================
// grid (8 m-tiles, 1024 imgs), block 256 (8 warps = 2m x 4n).
__global__ void __launch_bounds__(256, 2) conv2_hmma(
    const float* __restrict__ g, const float* __restrict__ bb,
    const float* __restrict__ mm, const float* __restrict__ vv)
{
    extern __shared__ char smem[];
    const int n     = blockIdx.y;
    const int mbase = blockIdx.x * 128;
    const int tid   = threadIdx.x;
    const int lane  = tid & 31, warp = tid >> 5;
    const int wm = warp >> 2, wn = warp & 3;
    const uint32_t smb = smem_u32(smem);

    float* s_scl = (float*)(smem + SM_BN);
    float* s_nm  = (float*)(smem + SM_BN + 512);
    float* s_bi  = (float*)(smem + SM_BN + 1024);
    if (tid < 128) {
        float sc = g[tid] * rsqrtf(vv[tid] + 1e-5f);
        s_scl[tid] = sc; s_nm[tid] = -mm[tid]; s_bi[tid] = bb[tid];
    }

    float acc[4][4][4];
#pragma unroll
    for (int a = 0; a < 4; a++)
#pragma unroll
        for (int b = 0; b < 4; b++)
#pragma unroll
            for (int c = 0; c < 4; c++) acc[a][b][c] = 0.f;

    const int row = tid >> 1, half = tid & 1;
    const uint4 z4 = make_uint4(0, 0, 0, 0);

#pragma unroll 1
    for (int kk = 0; kk < 9; kk++) {
        const int ky = kk / 3 - 1, kx = kk % 3 - 1;
        __syncthreads();
        // A slab: 128 px x 64 cin bf16, SW128 swizzle, zero-padded at borders
        {
            int px = mbase + row;
            int h = (px >> 5) + ky, w = (px & 31) + kx;
            bool ok = (unsigned)h < 32u && (unsigned)w < 32u;
            const uint4* src = (const uint4*)(g_s1 + ((size_t)(n * 1024 + h * 32 + w) * 64 + half * 32));
#pragma unroll
            for (int j = 0; j < 4; j++) {
                uint4 v = ok ? __ldg(src + j) : z4;
                *(uint4*)(smem + SM_A + SWZ(row * 128 + half * 64 + j * 16)) = v;
            }
        }
        // B slabs: 3 splits x 128 co x 64 cin, rows padded to 144B
#pragma unroll 1
        for (int it = tid; it < 3 * 128 * 8; it += 256) {
            int s = it >> 10, r = it & 1023, co = r >> 3, q = r & 7;
            const uint4* src = (const uint4*)(g_w2s + ((size_t)(s * 9 + kk) * 128 + co) * 64 + q * 8);
            *(uint4*)(smem + SM_B + s * SM_BSLAB + co * 144 + q * 16) = __ldg(src);
        }
        __syncthreads();

#pragma unroll
        for (int ks = 0; ks < 4; ks++) {
            uint32_t afr[4][4];
#pragma unroll
            for (int mi = 0; mi < 4; mi++) {
                int arow = wm * 64 + mi * 16 + (lane & 7) + ((lane >> 3) & 1) * 8;
                int acol = ks * 32 + ((lane >> 4) & 1) * 16;
                uint32_t addr = smb + SM_A + SWZ(arow * 128 + acol);
                LDMATRIX_X4(afr[mi], addr);
            }
#pragma unroll
            for (int s = 0; s < 3; s++) {
#pragma unroll
                for (int nj = 0; nj < 4; nj++) {
                    int nn = wn * 32 + nj * 8 + (lane >> 2);
                    int k0 = ks * 16 + (lane & 3) * 2;
                    const char* bp = smem + SM_B + s * SM_BSLAB + nn * 144 + k0 * 2;
                    uint32_t b0 = *(const uint32_t*)bp;
                    uint32_t b1 = *(const uint32_t*)(bp + 16);
#pragma unroll
                    for (int mi = 0; mi < 4; mi++)
                        MMA_BF16(acc[mi][nj], afr[mi], b0, b1);
                }
            }
        }
    }

    // epilogue: BN, write [n][px][128]
    float* obase = g_pre2 + (size_t)n * 1024 * 128;
#pragma unroll
    for (int mi = 0; mi < 4; mi++) {
        int px0 = mbase + wm * 64 + mi * 16 + (lane >> 2);
#pragma unroll
        for (int nj = 0; nj < 4; nj++) {
            int co = wn * 32 + nj * 8 + (lane & 3) * 2;
            float sc0 = s_scl[co], sc1 = s_scl[co + 1];
            float nm0 = s_nm[co],  nm1 = s_nm[co + 1];
            float bi0 = s_bi[co],  bi1 = s_bi[co + 1];
            float2 v0 = make_float2(fmaf(acc[mi][nj][0] + nm0, sc0, bi0),
                                    fmaf(acc[mi][nj][1] + nm1, sc1, bi1));
            float2 v1 = make_float2(fmaf(acc[mi][nj][2] + nm0, sc0, bi0),
                                    fmaf(acc[mi][nj][3] + nm1, sc1, bi1));
            *(float2*)(obase + (size_t)px0 * 128 + co)       = v0;
            *(float2*)(obase + (size_t)(px0 + 8) * 128 + co) = v1;
        }
    }
}

// ======================= conv3: 128->256, HMMA implicit GEMM =======================
// grid (4 = 2mt x 2nt, 1024 imgs), block 256. 18 chunks (kk x cinchunk).
__global__ void __launch_bounds__(256, 2) conv3_hmma(
    const float* __restrict__ g, const float* __restrict__ bb,
    const float* __restrict__ mm, const float* __restrict__ vv)
{
    extern __shared__ char smem[];
    const int n  = blockIdx.y;
    const int mt = blockIdx.x >> 1, nt = blockIdx.x & 1;
    const int tid  = threadIdx.x;
    const int lane = tid & 31, warp = tid >> 5;
    const int wm = warp >> 2, wn = warp & 3;
    const uint32_t smb = smem_u32(smem);

    float* s_scl = (float*)(smem + SM_BN);
    float* s_nm  = (float*)(smem + SM_BN + 512);
    float* s_bi  = (float*)(smem + SM_BN + 1024);
    if (tid < 128) {
        int c = nt * 128 + tid;
        float sc = g[c] * rsqrtf(vv[c] + 1e-5f);
        s_scl[tid] = sc; s_nm[tid] = -mm[c]; s_bi[tid] = bb[c];
    }

    float acc[4][4][4];
#pragma unroll
    for (int a = 0; a < 4; a++)
#pragma unroll
        for (int b = 0; b < 4; b++)
#pragma unroll
            for (int c = 0; c < 4; c++) acc[a][b][c] = 0.f;

    const int row = tid >> 1, half = tid & 1;
    const uint4 z4 = make_uint4(0, 0, 0, 0);

#pragma unroll 1
    for (int ch = 0; ch < 18; ch++) {
        const int kk = ch >> 1, cc = ch & 1;
        const int ky = kk / 3 - 1, kx = kk % 3 - 1;
        __syncthreads();
        // A slab from g_s2 [n][256px][128cin], take cin chunk cc
        {
            int px = mt * 128 + row;
            int h = (px >> 4) + ky, w = (px & 15) + kx;
            bool ok = (unsigned)h < 16u && (unsigned)w < 16u;
            const uint4* src = (const uint4*)(g_s2 + ((size_t)(n * 256 + h * 16 + w) * 128 + cc * 64 + half * 32));
#pragma unroll
            for (int j = 0; j < 4; j++) {
                uint4 v = ok ? __ldg(src + j) : z4;
                *(uint4*)(smem + SM_A + SWZ(row * 128 + half * 64 + j * 16)) = v;
            }
        }
        // B slabs: [s][kk][cc][nt][co][cin]
#pragma unroll 1
        for (int it = tid; it < 3 * 128 * 8; it += 256) {
            int s = it >> 10, r = it & 1023, co = r >> 3, q = r & 7;
            size_t bidx = (size_t)s * 294912 + ((size_t)(((kk * 2 + cc) * 2 + nt) * 128 + co)) * 64 + q * 8;
            *(uint4*)(smem + SM_B + s * SM_BSLAB + co * 144 + q * 16) = __ldg((const uint4*)(g_w3s + bidx));
        }
        __syncthreads();

#pragma unroll
        for (int ks = 0; ks < 4; ks++) {
            uint32_t afr[4][4];
#pragma unroll
            for (int mi = 0; mi < 4; mi++) {
                int arow = wm * 64 + mi * 16 + (lane & 7) + ((lane >> 3) & 1) * 8;
                int acol = ks * 32 + ((lane >> 4) & 1) * 16;
                uint32_t addr = smb + SM_A + SWZ(arow * 128 + acol);
                LDMATRIX_X4(afr[mi], addr);
            }
#pragma unroll
            for (int s = 0; s < 3; s++) {
#pragma unroll
                for (int nj = 0; nj < 4; nj++) {
                    int nn = wn * 32 + nj * 8 + (lane >> 2);
                    int k0 = ks * 16 + (lane & 3) * 2;
                    const char* bp = smem + SM_B + s * SM_BSLAB + nn * 144 + k0 * 2;
                    uint32_t b0 = *(const uint32_t*)bp;
                    uint32_t b1 = *(const uint32_t*)(bp + 16);
#pragma unroll
                    for (int mi = 0; mi < 4; mi++)
                        MMA_BF16(acc[mi][nj], afr[mi], b0, b1);
                }
            }
        }
    }

    // epilogue: BN, write [n][px][256] (cols nt*128..+128)
    float* obase = g_pre3 + (size_t)n * 256 * 256 + nt * 128;
#pragma unroll
    for (int mi = 0; mi < 4; mi++) {
        int px0 = mt * 128 + wm * 64 + mi * 16 + (lane >> 2);
#pragma unroll
        for (int nj = 0; nj < 4; nj++) {
            int co = wn * 32 + nj * 8 + (lane & 3) * 2;
            float sc0 = s_scl[co], sc1 = s_scl[co + 1];
            float nm0 = s_nm[co],  nm1 = s_nm[co + 1];
            float bi0 = s_bi[co],  bi1 = s_bi[co + 1];
            float2 v0 = make_float2(fmaf(acc[mi][nj][0] + nm0, sc0, bi0),
                                    fmaf(acc[mi][nj][1] + nm1, sc1, bi1));
            float2 v1 = make_float2(fmaf(acc[mi][nj][2] + nm0, sc0, bi0),
                                    fmaf(acc[mi][nj][3] + nm1, sc1, bi1));
            *(float2*)(obase + (size_t)px0 * 256 + co)       = v0;
            *(float2*)(obase + (size_t)(px0 + 8) * 256 + co) = v1;
        }
    }
}

// ======================= lif2 + pool: pre2 -> s2 bf16 =======================
__global__ void lif2_pool()
{
    const int i = blockIdx.x * 256 + threadIdx.x;   // B*16*16*128
    const int co = i & 127;
    const int wo = (i >> 7) & 15;
    const int ho = (i >> 11) & 15;
    const int b  = i >> 15;

    float v00 = 0.f, v01 = 0.f, v10 = 0.f, v11 = 0.f;
#pragma unroll
    for (int t = 0; t < T_STEPS; t++) {
        const float* p = g_pre2 + ((size_t)((t * BATCH + b) * 1024 + (2 * ho) * 32 + 2 * wo)) * 128 + co;
        float x00 = p[0], x01 = p[128], x10 = p[32 * 128], x11 = p[33 * 128];
        v00 += (x00 - v00) * 0.5f; float s00 = (v00 >= 1.f) ? 1.f : 0.f; v00 *= (1.f - s00);
        v01 += (x01 - v01) * 0.5f; float s01 = (v01 >= 1.f) ? 1.f : 0.f; v01 *= (1.f - s01);
        v10 += (x10 - v10) * 0.5f; float s10 = (v10 >= 1.f) ? 1.f : 0.f; v10 *= (1.f - s10);
        v11 += (x11 - v11) * 0.5f; float s11 = (v11 >= 1.f) ? 1.f : 0.f; v11 *= (1.f - s11);
        float s = fmaxf(fmaxf(s00, s01), fmaxf(s10, s11));
        g_s2[((size_t)(t * BATCH + b) * 256 + ho * 16 + wo) * 128 + co] = __float2bfloat16(s);
    }
}

// ======================= lif3 + pool: pre3 -> s3 fp32 (c*64+h*8+w order) =======================
__global__ void lif3_pool()
{
    const int i = blockIdx.x * 256 + threadIdx.x;   // B*8*8*256
    const int co = i & 255;
    const int wo = (i >> 8) & 7;
    const int ho = (i >> 11) & 7;
    const int b  = i >> 14;

    float v00 = 0.f, v01 = 0.f, v10 = 0.f, v11 = 0.f;
#pragma unroll
    for (int t = 0; t < T_STEPS; t++) {
        const float* p = g_pre3 + ((size_t)((t * BATCH + b) * 256 + (2 * ho) * 16 + 2 * wo)) * 256 + co;
        float x00 = p[0], x01 = p[256], x10 = p[16 * 256], x11 = p[17 * 256];
        v00 += (x00 - v00) * 0.5f; float s00 = (v00 >= 1.f) ? 1.f : 0.f; v00 *= (1.f - s00);
        v01 += (x01 - v01) * 0.5f; float s01 = (v01 >= 1.f) ? 1.f : 0.f; v01 *= (1.f - s01);
        v10 += (x10 - v10) * 0.5f; float s10 = (v10 >= 1.f) ? 1.f : 0.f; v10 *= (1.f - s10);
        v11 += (x11 - v11) * 0.5f; float s11 = (v11 >= 1.f) ? 1.f : 0.f; v11 *= (1.f - s11);
        float s = fmaxf(fmaxf(s00, s01), fmaxf(s10, s11));
        g_s3[(size_t)(t * BATCH + b) * 16384 + co * 64 + ho * 8 + wo] = s;
    }
}

// ======================= FC GEMM =======================
__global__ void __launch_bounds__(256) fc_gemm(const float* __restrict__ W)
{
    const int f0 = blockIdx.x * 64;
    const int m0 = blockIdx.y * 64;
    const int tid = threadIdx.x;
    const int tx = tid & 15, ty = tid >> 4;

    __shared__ float As[16][64];
    __shared__ float Bs[16][64];

    float acc[4][4];
#pragma unroll
    for (int i = 0; i < 4; i++)
#pragma unroll
        for (int j = 0; j < 4; j++) acc[i][j] = 0.f;

    const int lrow = tid >> 2;
    const int lk   = (tid & 3) * 4;

    for (int k0 = 0; k0 < 16384; k0 += 16) {
        float4 a = *(const float4*)(g_s3 + (size_t)(m0 + lrow) * 16384 + k0 + lk);
        float4 b = *(const float4*)(W + (size_t)(f0 + lrow) * 16384 + k0 + lk);
        As[lk + 0][lrow] = a.x; As[lk + 1][lrow] = a.y;
        As[lk + 2][lrow] = a.z; As[lk + 3][lrow] = a.w;
        Bs[lk + 0][lrow] = b.x; Bs[lk + 1][lrow] = b.y;
        Bs[lk + 2][lrow] = b.z; Bs[lk + 3][lrow] = b.w;
        __syncthreads();
#pragma unroll
        for (int kk = 0; kk < 16; kk++) {
            float4 ra = *(const float4*)&As[kk][ty * 4];
            float4 rb = *(const float4*)&Bs[kk][tx * 4];
            float av[4] = {ra.x, ra.y, ra.z, ra.w};
            float bv[4] = {rb.x, rb.y, rb.z, rb.w};
#pragma unroll
            for (int i = 0; i < 4; i++)
#pragma unroll
                for (int j = 0; j < 4; j++)
                    acc[i][j] = fmaf(av[i], bv[j], acc[i][j]);
        }
        __syncthreads();
    }

#pragma unroll
    for (int i = 0; i < 4; i++)
#pragma unroll
        for (int j = 0; j < 4; j++)
            g_fc[(m0 + ty * 4 + i) * 512 + f0 + tx * 4 + j] = acc[i][j];
}

// ======================= LIF fc + mean =======================
__global__ void lif_fc_mean()
{
    const int i = blockIdx.x * 256 + threadIdx.x;
    float v = 0.f, sum = 0.f;
#pragma unroll
    for (int t = 0; t < T_STEPS; t++) {
        float xv = g_fc[t * (BATCH * 512) + i];
        v = v + (xv - v) * 0.5f;
        float s = (v >= 1.0f) ? 1.0f : 0.0f;
        v = v * (1.0f - s);
        sum += s;
    }
    g_feat[i] = sum * 0.125f;
}

// ======================= cosine head =======================
__device__ __forceinline__ float blk_sum(float v, float* red)
{
    const int lane = threadIdx.x & 31, wp = threadIdx.x >> 5;
#pragma unroll
    for (int o = 16; o > 0; o >>= 1) v += __shfl_down_sync(0xffffffffu, v, o);
    if (lane == 0) red[wp] = v;
    __syncthreads();
    float r = (threadIdx.x < 8) ? red[threadIdx.x] : 0.f;
    if (wp == 0) {
#pragma unroll
        for (int o = 4; o > 0; o >>= 1) r += __shfl_down_sync(0xffu, r, o);
        if (lane == 0) red[0] = r;
    }
    __syncthreads();
    float res = red[0];
    __syncthreads();
    return res;
}

__global__ void final_head(const float* __restrict__ protos, float* __restrict__ out)
{
    const int b = blockIdx.x;
    const int tid = threadIdx.x;
    __shared__ float sf[512];
    __shared__ float red[8];

    for (int i = tid; i < 512; i += 256) sf[i] = g_feat[b * 512 + i];
    __syncthreads();

    float ps = 0.f;
    for (int i = tid; i < 512; i += 256) ps += sf[i] * sf[i];
    float nf = sqrtf(blk_sum(ps, red));
    nf = fmaxf(nf, 1e-12f);

    for (int p = 0; p < 10; p++) {
        float pd = 0.f, pq = 0.f;
        for (int i = tid; i < 512; i += 256) {
            float pv = __ldg(&protos[p * 512 + i]);
            pd += sf[i] * pv;
            pq += pv * pv;
        }
        pd = blk_sum(pd, red);
        pq = blk_sum(pq, red);
        if (tid == 0)
            out[b * 10 + p] = 10.f * pd / (nf * fmaxf(sqrtf(pq), 1e-12f));
    }
}

// ======================= launch =======================
extern "C" void kernel_launch(void* const* d_in, const int* in_sizes, int n_in,
                              void* d_out, int out_size)
{
    const float* x = nullptr;
    const float* w1 = nullptr; const float* w2 = nullptr; const float* w3 = nullptr;
    const float* fcw = nullptr; const float* protos = nullptr;
    const float* bn64[4]  = {nullptr, nullptr, nullptr, nullptr};
    const float* bn128[4] = {nullptr, nullptr, nullptr, nullptr};
    const float* bn256[4] = {nullptr, nullptr, nullptr, nullptr};
    int c64 = 0, c128 = 0, c256 = 0;

    for (int i = 0; i < n_in; i++) {
        const float* p = (const float*)d_in[i];
        switch (in_sizes[i]) {
            case 3145728: x = p; break;
            case 1728:    w1 = p; break;
            case 73728:   w2 = p; break;
            case 294912:  w3 = p; break;
            case 8388608: fcw = p; break;
            case 5120:    protos = p; break;
            case 64:  if (c64  < 4) bn64[c64++]   = p; break;
            case 128: if (c128 < 4) bn128[c128++] = p; break;
            case 256: if (c256 < 4) bn256[c256++] = p; break;
            default: break;
        }
    }
    if (!x || !w1 || !w2 || !w3 || !fcw || !protos) return;

    cudaFuncSetAttribute(conv2_hmma, cudaFuncAttributeMaxDynamicSharedMemorySize, SMEM_BYTES);
    cudaFuncSetAttribute(conv3_hmma, cudaFuncAttributeMaxDynamicSharedMemorySize, SMEM_BYTES);

    wprep2<<<288, 256>>>(w2);
    wprep3<<<1152, 256>>>(w3);
    conv1_bn<<<dim3(4, 8, NIMG), 256>>>(x, w1, bn64[0], bn64[1], bn64[2], bn64[3]);
    lif1_kernel<<<32768, 256>>>();
    conv2_hmma<<<dim3(8, NIMG), 256, SMEM_BYTES>>>(bn128[0], bn128[1], bn128[2], bn128[3]);
    lif2_pool<<<16384, 256>>>();
    conv3_hmma<<<dim3(4, NIMG), 256, SMEM_BYTES>>>(bn256[0], bn256[1], bn256[2], bn256[3]);
    lif3_pool<<<8192, 256>>>();
    fc_gemm<<<dim3(8, 16), 256>>>(fcw);
    lif_fc_mean<<<256, 256>>>();
    final_head<<<BATCH, 256>>>(protos, (float*)d_out);
}

// round 15
// speedup vs baseline: 1.0053x; 1.0029x over previous
#include <cuda_runtime.h>
#include <cuda_bf16.h>
#include <cstdint>

#define T_STEPS 8
#define BATCH   128
#define NIMG    (T_STEPS * BATCH)   // 1024

// ======================= helpers =======================
__device__ __forceinline__ uint32_t smem_u32(const void* p) {
    uint32_t a;
    asm("{ .reg .u64 t; cvta.to.shared.u64 t, %1; cvt.u32.u64 %0, t; }" : "=r"(a) : "l"(p));
    return a;
}
#define SWZ(off) ((off) ^ (((off) >> 3) & 0x70))

#define MMA_BF16(acc, a, b0, b1) \
    asm volatile("mma.sync.aligned.m16n8k16.row.col.f32.bf16.bf16.f32 " \
        "{%0,%1,%2,%3}, {%4,%5,%6,%7}, {%8,%9}, {%0,%1,%2,%3};" \
        : "+f"((acc)[0]), "+f"((acc)[1]), "+f"((acc)[2]), "+f"((acc)[3]) \
        : "r"((a)[0]), "r"((a)[1]), "r"((a)[2]), "r"((a)[3]), "r"(b0), "r"(b1))

#define LDMATRIX_X4(a, addr) \
    asm volatile("ldmatrix.sync.aligned.m8n8.x4.shared.b16 {%0,%1,%2,%3}, [%4];" \
        : "=r"((a)[0]), "=r"((a)[1]), "=r"((a)[2]), "=r"((a)[3]) : "r"(addr))

// ======================= scratch =======================
__device__ __align__(16) float         g_pre1[NIMG * 1024 * 64];          // conv1 out [n][px][64c]
__device__ __align__(16) __nv_bfloat16 g_s1  [NIMG * 1024 * 64];          // spikes bf16
__device__ __align__(16) float         g_pre2[(size_t)NIMG * 1024 * 128]; // conv2 out [n][px][128c]
__device__ __align__(16) __nv_bfloat16 g_s2  [NIMG * 256 * 128];          // pooled spikes bf16
__device__ __align__(16) float         g_pre3[NIMG * 256 * 256];          // conv3 out [n][px][256c]
__device__ __align__(16) float         g_s3  [NIMG * 16384];              // fc input fp32 [n][c*64+h*8+w]
__device__ __align__(16) __nv_bfloat16 g_w2s [3 * 9 * 128 * 64];          // [s][kk][co][cin]
__device__ __align__(16) __nv_bfloat16 g_w3s [3 * 9 * 2 * 2 * 128 * 64];  // [s][kk][cc][nt][co][cin]
__device__ float g_fc  [NIMG * 512];
__device__ float g_feat[BATCH * 512];

// smem layout (bytes): BN at 16 (3*512), A slab at 2048 (16KB, SW128),
// B slabs at 18432 (3 x 18432, rows padded to 144B)
#define SM_BN    16
#define SM_A     2048
#define SM_B     18432
#define SM_BSLAB 18432
#define SMEM_BYTES 73728

// ======================= weight splitting (exact 8+8+8) =======================
__device__ __forceinline__ void split3(float w, __nv_bfloat16& h, __nv_bfloat16& m, __nv_bfloat16& l)
{
    h = __float2bfloat16_rz(w);
    float r1 = w - __bfloat162float(h);
    m = __float2bfloat16_rz(r1);
    float r2 = r1 - __bfloat162float(m);
    l = __float2bfloat16_rz(r2);
}

__global__ void wprep2(const float* __restrict__ w2)
{
    int i = blockIdx.x * 256 + threadIdx.x;          // 128*64*9 = 73728
    if (i >= 128 * 64 * 9) return;
    int co = i / 576, r = i % 576, cin = r / 9, kk = r % 9;
    __nv_bfloat16 h, m, l;
    split3(w2[co * 576 + cin * 9 + kk], h, m, l);
    int base = kk * 8192 + co * 64 + cin;
    g_w2s[base] = h; g_w2s[9 * 8192 + base] = m; g_w2s[18 * 8192 + base] = l;
}

__global__ void wprep3(const float* __restrict__ w3)
{
    int i = blockIdx.x * 256 + threadIdx.x;          // 256*128*9 = 294912
    if (i >= 256 * 128 * 9) return;
    int co = i / 1152, r = i % 1152, cin = r / 9, kk = r % 9;
    __nv_bfloat16 h, m, l;
    split3(w3[co * 1152 + cin * 9 + kk], h, m, l);
    int nt = co >> 7, col = co & 127, cc = cin >> 6, cinl = cin & 63;
    int idx = ((((kk * 2 + cc) * 2 + nt) * 128 + col) * 64 + cinl);
    g_w3s[idx] = h;
    g_w3s[294912 + idx] = m;
    g_w3s[2 * 294912 + idx] = l;
}

// ======================= conv1: 3->64, scalar, out [n][px][c] =======================
__global__ void __launch_bounds__(256) conv1_bn(
    const float* __restrict__ x, const float* __restrict__ w,
    const float* __restrict__ g, const float* __restrict__ bb,
    const float* __restrict__ mm, const float* __restrict__ vv)
{
    const int n   = blockIdx.z;
    const int co0 = blockIdx.y * 8;
    const int pix = blockIdx.x * 256 + threadIdx.x;
    const int h = pix >> 5, wi = pix & 31;

    __shared__ float ws[8 * 27];
    if (threadIdx.x < 216) ws[threadIdx.x] = w[co0 * 27 + threadIdx.x];
    __syncthreads();

    const float* xb = x + n * 3 * 1024;
    float acc[8];
#pragma unroll
    for (int j = 0; j < 8; j++) acc[j] = 0.f;

#pragma unroll
    for (int c = 0; c < 3; c++)
#pragma unroll
        for (int ky = 0; ky < 3; ky++)
#pragma unroll
            for (int kx = 0; kx < 3; kx++) {
                int ih = h + ky - 1, iw = wi + kx - 1;
                float v = 0.f;
                if ((unsigned)ih < 32u && (unsigned)iw < 32u)
                    v = __ldg(&xb[c * 1024 + ih * 32 + iw]);
                int k = c * 9 + ky * 3 + kx;
#pragma unroll
                for (int j = 0; j < 8; j++)
                    acc[j] = fmaf(v, ws[j * 27 + k], acc[j]);
            }

#pragma unroll
    for (int j = 0; j < 8; j++) {
        int c = co0 + j;
        float scale = g[c] * rsqrtf(vv[c] + 1e-5f);
        g_pre1[((size_t)n * 1024 + pix) * 64 + c] = (acc[j] - mm[c]) * scale + bb[c];
    }
}

// ======================= lif1: pre1 -> bf16 spikes =======================
__global__ void lif1_kernel()
{
    const size_t i = (size_t)blockIdx.x * 256 + threadIdx.x;   // B*1024*64
    const size_t stride = (size_t)BATCH * 1024 * 64;
    float v = 0.f;
#pragma unroll
    for (int t = 0; t < T_STEPS; t++) {
        float xv = g_pre1[t * stride + i];
        v = v + (xv - v) * 0.5f;
        float s = (v >= 1.0f) ? 1.0f : 0.0f;
        g_s1[t * stride + i] = __float2bfloat16(s);
        v = v * (1.0f - s);
    }
}

// ======================= conv2: 64->128, HMMA implicit GEMM =======================
// grid (8 m-tiles, 1024 imgs), block 256 (8 warps = 2m x 4n).
__global__ void __launch_bounds__(256, 2) conv2_hmma(
    const float* __restrict__ g, const float* __restrict__ bb,
    const float* __restrict__ mm, const float* __restrict__ vv)
{
    extern __shared__ char smem[];
    const int n     = blockIdx.y;
    const int mbase = blockIdx.x * 128;
    const int tid   = threadIdx.x;
    const int lane  = tid & 31, warp = tid >> 5;
    const int wm = warp >> 2, wn = warp & 3;
    const uint32_t smb = smem_u32(smem);

    float* s_scl = (float*)(smem + SM_BN);
    float* s_nm  = (float*)(smem + SM_BN + 512);
    float* s_bi  = (float*)(smem + SM_BN + 1024);
    if (tid < 128) {
        float sc = g[tid] * rsqrtf(vv[tid] + 1e-5f);
        s_scl[tid] = sc; s_nm[tid] = -mm[tid]; s_bi[tid] = bb[tid];
    }

    float acc[4][4][4];
#pragma unroll
    for (int a = 0; a < 4; a++)
#pragma unroll
        for (int b = 0; b < 4; b++)
#pragma unroll
            for (int c = 0; c < 4; c++) acc[a][b][c] = 0.f;

    const int row = tid >> 1, half = tid & 1;
    const uint4 z4 = make_uint4(0, 0, 0, 0);

#pragma unroll 1
    for (int kk = 0; kk < 9; kk++) {
        const int ky = kk / 3 - 1, kx = kk % 3 - 1;
        __syncthreads();
        // A slab: 128 px x 64 cin bf16, SW128 swizzle, zero-padded at borders
        {
            int px = mbase + row;
            int h = (px >> 5) + ky, w = (px & 31) + kx;
            bool ok = (unsigned)h < 32u && (unsigned)w < 32u;
            const uint4* src = (const uint4*)(g_s1 + ((size_t)(n * 1024 + h * 32 + w) * 64 + half * 32));
#pragma unroll
            for (int j = 0; j < 4; j++) {
                uint4 v = ok ? __ldg(src + j) : z4;
                *(uint4*)(smem + SM_A + SWZ(row * 128 + half * 64 + j * 16)) = v;
            }
        }
        // B slabs: 3 splits x 128 co x 64 cin, rows padded to 144B
#pragma unroll 1
        for (int it = tid; it < 3 * 128 * 8; it += 256) {
            int s = it >> 10, r = it & 1023, co = r >> 3, q = r & 7;
            const uint4* src = (const uint4*)(g_w2s + ((size_t)(s * 9 + kk) * 128 + co) * 64 + q * 8);
            *(uint4*)(smem + SM_B + s * SM_BSLAB + co * 144 + q * 16) = __ldg(src);
        }
        __syncthreads();

#pragma unroll
        for (int ks = 0; ks < 4; ks++) {
            uint32_t afr[4][4];
#pragma unroll
            for (int mi = 0; mi < 4; mi++) {
                int arow = wm * 64 + mi * 16 + (lane & 7) + ((lane >> 3) & 1) * 8;
                int acol = ks * 32 + ((lane >> 4) & 1) * 16;
                uint32_t addr = smb + SM_A + SWZ(arow * 128 + acol);
                LDMATRIX_X4(afr[mi], addr);
            }
#pragma unroll
            for (int s = 0; s < 3; s++) {
#pragma unroll
                for (int nj = 0; nj < 4; nj++) {
                    int nn = wn * 32 + nj * 8 + (lane >> 2);
                    int k0 = ks * 16 + (lane & 3) * 2;
                    const char* bp = smem + SM_B + s * SM_BSLAB + nn * 144 + k0 * 2;
                    uint32_t b0 = *(const uint32_t*)bp;
                    uint32_t b1 = *(const uint32_t*)(bp + 16);
#pragma unroll
                    for (int mi = 0; mi < 4; mi++)
                        MMA_BF16(acc[mi][nj], afr[mi], b0, b1);
                }
            }
        }
    }

    // epilogue: BN, write [n][px][128]
    float* obase = g_pre2 + (size_t)n * 1024 * 128;
#pragma unroll
    for (int mi = 0; mi < 4; mi++) {
        int px0 = mbase + wm * 64 + mi * 16 + (lane >> 2);
#pragma unroll
        for (int nj = 0; nj < 4; nj++) {
            int co = wn * 32 + nj * 8 + (lane & 3) * 2;
            float sc0 = s_scl[co], sc1 = s_scl[co + 1];
            float nm0 = s_nm[co],  nm1 = s_nm[co + 1];
            float bi0 = s_bi[co],  bi1 = s_bi[co + 1];
            float2 v0 = make_float2(fmaf(acc[mi][nj][0] + nm0, sc0, bi0),
                                    fmaf(acc[mi][nj][1] + nm1, sc1, bi1));
            float2 v1 = make_float2(fmaf(acc[mi][nj][2] + nm0, sc0, bi0),
                                    fmaf(acc[mi][nj][3] + nm1, sc1, bi1));
            *(float2*)(obase + (size_t)px0 * 128 + co)       = v0;
            *(float2*)(obase + (size_t)(px0 + 8) * 128 + co) = v1;
        }
    }
}

// ======================= conv3: 128->256, HMMA implicit GEMM =======================
// grid (4 = 2mt x 2nt, 1024 imgs), block 256. 18 chunks (kk x cinchunk).
__global__ void __launch_bounds__(256, 2) conv3_hmma(
    const float* __restrict__ g, const float* __restrict__ bb,
    const float* __restrict__ mm, const float* __restrict__ vv)
{
    extern __shared__ char smem[];
    const int n  = blockIdx.y;
    const int mt = blockIdx.x >> 1, nt = blockIdx.x & 1;
    const int tid  = threadIdx.x;
    const int lane = tid & 31, warp = tid >> 5;
    const int wm = warp >> 2, wn = warp & 3;
    const uint32_t smb = smem_u32(smem);

    float* s_scl = (float*)(smem + SM_BN);
    float* s_nm  = (float*)(smem + SM_BN + 512);
    float* s_bi  = (float*)(smem + SM_BN + 1024);
    if (tid < 128) {
        int c = nt * 128 + tid;
        float sc = g[c] * rsqrtf(vv[c] + 1e-5f);
        s_scl[tid] = sc; s_nm[tid] = -mm[c]; s_bi[tid] = bb[c];
    }

    float acc[4][4][4];
#pragma unroll
    for (int a = 0; a < 4; a++)
#pragma unroll
        for (int b = 0; b < 4; b++)
#pragma unroll
            for (int c = 0; c < 4; c++) acc[a][b][c] = 0.f;

    const int row = tid >> 1, half = tid & 1;
    const uint4 z4 = make_uint4(0, 0, 0, 0);

#pragma unroll 1
    for (int ch = 0; ch < 18; ch++) {
        const int kk = ch >> 1, cc = ch & 1;
        const int ky = kk / 3 - 1, kx = kk % 3 - 1;
        __syncthreads();
        // A slab from g_s2 [n][256px][128cin], take cin chunk cc
        {
            int px = mt * 128 + row;
            int h = (px >> 4) + ky, w = (px & 15) + kx;
            bool ok = (unsigned)h < 16u && (unsigned)w < 16u;
            const uint4* src = (const uint4*)(g_s2 + ((size_t)(n * 256 + h * 16 + w) * 128 + cc * 64 + half * 32));
#pragma unroll
            for (int j = 0; j < 4; j++) {
                uint4 v = ok ? __ldg(src + j) : z4;
                *(uint4*)(smem + SM_A + SWZ(row * 128 + half * 64 + j * 16)) = v;
            }
        }
        // B slabs: [s][kk][cc][nt][co][cin]
#pragma unroll 1
        for (int it = tid; it < 3 * 128 * 8; it += 256) {
            int s = it >> 10, r = it & 1023, co = r >> 3, q = r & 7;
            size_t bidx = (size_t)s * 294912 + ((size_t)(((kk * 2 + cc) * 2 + nt) * 128 + co)) * 64 + q * 8;
            *(uint4*)(smem + SM_B + s * SM_BSLAB + co * 144 + q * 16) = __ldg((const uint4*)(g_w3s + bidx));
        }
        __syncthreads();

#pragma unroll
        for (int ks = 0; ks < 4; ks++) {
            uint32_t afr[4][4];
#pragma unroll
            for (int mi = 0; mi < 4; mi++) {
                int arow = wm * 64 + mi * 16 + (lane & 7) + ((lane >> 3) & 1) * 8;
                int acol = ks * 32 + ((lane >> 4) & 1) * 16;
                uint32_t addr = smb + SM_A + SWZ(arow * 128 + acol);
                LDMATRIX_X4(afr[mi], addr);
            }
#pragma unroll
            for (int s = 0; s < 3; s++) {
#pragma unroll
                for (int nj = 0; nj < 4; nj++) {
                    int nn = wn * 32 + nj * 8 + (lane >> 2);
                    int k0 = ks * 16 + (lane & 3) * 2;
                    const char* bp = smem + SM_B + s * SM_BSLAB + nn * 144 + k0 * 2;
                    uint32_t b0 = *(const uint32_t*)bp;
                    uint32_t b1 = *(const uint32_t*)(bp + 16);
#pragma unroll
                    for (int mi = 0; mi < 4; mi++)
                        MMA_BF16(acc[mi][nj], afr[mi], b0, b1);
                }
            }
        }
    }

    // epilogue: BN, write [n][px][256] (cols nt*128..+128)
    float* obase = g_pre3 + (size_t)n * 256 * 256 + nt * 128;
#pragma unroll
    for (int mi = 0; mi < 4; mi++) {
        int px0 = mt * 128 + wm * 64 + mi * 16 + (lane >> 2);
#pragma unroll
        for (int nj = 0; nj < 4; nj++) {
            int co = wn * 32 + nj * 8 + (lane & 3) * 2;
            float sc0 = s_scl[co], sc1 = s_scl[co + 1];
            float nm0 = s_nm[co],  nm1 = s_nm[co + 1];
            float bi0 = s_bi[co],  bi1 = s_bi[co + 1];
            float2 v0 = make_float2(fmaf(acc[mi][nj][0] + nm0, sc0, bi0),
                                    fmaf(acc[mi][nj][1] + nm1, sc1, bi1));
            float2 v1 = make_float2(fmaf(acc[mi][nj][2] + nm0, sc0, bi0),
                                    fmaf(acc[mi][nj][3] + nm1, sc1, bi1));
            *(float2*)(obase + (size_t)px0 * 256 + co)       = v0;
            *(float2*)(obase + (size_t)(px0 + 8) * 256 + co) = v1;
        }
    }
}

// ======================= lif2 + pool: pre2 -> s2 bf16 =======================
__global__ void lif2_pool()
{
    const int i = blockIdx.x * 256 + threadIdx.x;   // B*16*16*128
    const int co = i & 127;
    const int wo = (i >> 7) & 15;
    const int ho = (i >> 11) & 15;
    const int b  = i >> 15;

    float v00 = 0.f, v01 = 0.f, v10 = 0.f, v11 = 0.f;
#pragma unroll
    for (int t = 0; t < T_STEPS; t++) {
        const float* p = g_pre2 + ((size_t)((t * BATCH + b) * 1024 + (2 * ho) * 32 + 2 * wo)) * 128 + co;
        float x00 = p[0], x01 = p[128], x10 = p[32 * 128], x11 = p[33 * 128];
        v00 += (x00 - v00) * 0.5f; float s00 = (v00 >= 1.f) ? 1.f : 0.f; v00 *= (1.f - s00);
        v01 += (x01 - v01) * 0.5f; float s01 = (v01 >= 1.f) ? 1.f : 0.f; v01 *= (1.f - s01);
        v10 += (x10 - v10) * 0.5f; float s10 = (v10 >= 1.f) ? 1.f : 0.f; v10 *= (1.f - s10);
        v11 += (x11 - v11) * 0.5f; float s11 = (v11 >= 1.f) ? 1.f : 0.f; v11 *= (1.f - s11);
        float s = fmaxf(fmaxf(s00, s01), fmaxf(s10, s11));
        g_s2[((size_t)(t * BATCH + b) * 256 + ho * 16 + wo) * 128 + co] = __float2bfloat16(s);
    }
}

// ======================= lif3 + pool: pre3 -> s3 fp32 (c*64+h*8+w order) =======================
__global__ void lif3_pool()
{
    const int i = blockIdx.x * 256 + threadIdx.x;   // B*8*8*256
    const int co = i & 255;
    const int wo = (i >> 8) & 7;
    const int ho = (i >> 11) & 7;
    const int b  = i >> 14;

    float v00 = 0.f, v01 = 0.f, v10 = 0.f, v11 = 0.f;
#pragma unroll
    for (int t = 0; t < T_STEPS; t++) {
        const float* p = g_pre3 + ((size_t)((t * BATCH + b) * 256 + (2 * ho) * 16 + 2 * wo)) * 256 + co;
        float x00 = p[0], x01 = p[256], x10 = p[16 * 256], x11 = p[17 * 256];
        v00 += (x00 - v00) * 0.5f; float s00 = (v00 >= 1.f) ? 1.f : 0.f; v00 *= (1.f - s00);
        v01 += (x01 - v01) * 0.5f; float s01 = (v01 >= 1.f) ? 1.f : 0.f; v01 *= (1.f - s01);
        v10 += (x10 - v10) * 0.5f; float s10 = (v10 >= 1.f) ? 1.f : 0.f; v10 *= (1.f - s10);
        v11 += (x11 - v11) * 0.5f; float s11 = (v11 >= 1.f) ? 1.f : 0.f; v11 *= (1.f - s11);
        float s = fmaxf(fmaxf(s00, s01), fmaxf(s10, s11));
        g_s3[(size_t)(t * BATCH + b) * 16384 + co * 64 + ho * 8 + wo] = s;
    }
}

// ======================= FC GEMM =======================
__global__ void __launch_bounds__(256) fc_gemm(const float* __restrict__ W)
{
    const int f0 = blockIdx.x * 64;
    const int m0 = blockIdx.y * 64;
    const int tid = threadIdx.x;
    const int tx = tid & 15, ty = tid >> 4;

    __shared__ float As[16][64];
    __shared__ float Bs[16][64];

    float acc[4][4];
#pragma unroll
    for (int i = 0; i < 4; i++)
#pragma unroll
        for (int j = 0; j < 4; j++) acc[i][j] = 0.f;

    const int lrow = tid >> 2;
    const int lk   = (tid & 3) * 4;

    for (int k0 = 0; k0 < 16384; k0 += 16) {
        float4 a = *(const float4*)(g_s3 + (size_t)(m0 + lrow) * 16384 + k0 + lk);
        float4 b = *(const float4*)(W + (size_t)(f0 + lrow) * 16384 + k0 + lk);
        As[lk + 0][lrow] = a.x; As[lk + 1][lrow] = a.y;
        As[lk + 2][lrow] = a.z; As[lk + 3][lrow] = a.w;
        Bs[lk + 0][lrow] = b.x; Bs[lk + 1][lrow] = b.y;
        Bs[lk + 2][lrow] = b.z; Bs[lk + 3][lrow] = b.w;
        __syncthreads();
#pragma unroll
        for (int kk = 0; kk < 16; kk++) {
            float4 ra = *(const float4*)&As[kk][ty * 4];
            float4 rb = *(const float4*)&Bs[kk][tx * 4];
            float av[4] = {ra.x, ra.y, ra.z, ra.w};
            float bv[4] = {rb.x, rb.y, rb.z, rb.w};
#pragma unroll
            for (int i = 0; i < 4; i++)
#pragma unroll
                for (int j = 0; j < 4; j++)
                    acc[i][j] = fmaf(av[i], bv[j], acc[i][j]);
        }
        __syncthreads();
    }

#pragma unroll
    for (int i = 0; i < 4; i++)
#pragma unroll
        for (int j = 0; j < 4; j++)
            g_fc[(m0 + ty * 4 + i) * 512 + f0 + tx * 4 + j] = acc[i][j];
}

// ======================= LIF fc + mean =======================
__global__ void lif_fc_mean()
{
    const int i = blockIdx.x * 256 + threadIdx.x;
    float v = 0.f, sum = 0.f;
#pragma unroll
    for (int t = 0; t < T_STEPS; t++) {
        float xv = g_fc[t * (BATCH * 512) + i];
        v = v + (xv - v) * 0.5f;
        float s = (v >= 1.0f) ? 1.0f : 0.0f;
        v = v * (1.0f - s);
        sum += s;
    }
    g_feat[i] = sum * 0.125f;
}

// ======================= cosine head =======================
__device__ __forceinline__ float blk_sum(float v, float* red)
{
    const int lane = threadIdx.x & 31, wp = threadIdx.x >> 5;
#pragma unroll
    for (int o = 16; o > 0; o >>= 1) v += __shfl_down_sync(0xffffffffu, v, o);
    if (lane == 0) red[wp] = v;
    __syncthreads();
    float r = (threadIdx.x < 8) ? red[threadIdx.x] : 0.f;
    if (wp == 0) {
#pragma unroll
        for (int o = 4; o > 0; o >>= 1) r += __shfl_down_sync(0xffu, r, o);
        if (lane == 0) red[0] = r;
    }
    __syncthreads();
    float res = red[0];
    __syncthreads();
    return res;
}

__global__ void final_head(const float* __restrict__ protos, float* __restrict__ out)
{
    const int b = blockIdx.x;
    const int tid = threadIdx.x;
    __shared__ float sf[512];
    __shared__ float red[8];

    for (int i = tid; i < 512; i += 256) sf[i] = g_feat[b * 512 + i];
    __syncthreads();

    float ps = 0.f;
    for (int i = tid; i < 512; i += 256) ps += sf[i] * sf[i];
    float nf = sqrtf(blk_sum(ps, red));
    nf = fmaxf(nf, 1e-12f);

    for (int p = 0; p < 10; p++) {
        float pd = 0.f, pq = 0.f;
        for (int i = tid; i < 512; i += 256) {
            float pv = __ldg(&protos[p * 512 + i]);
            pd += sf[i] * pv;
            pq += pv * pv;
        }
        pd = blk_sum(pd, red);
        pq = blk_sum(pq, red);
        if (tid == 0)
            out[b * 10 + p] = 10.f * pd / (nf * fmaxf(sqrtf(pq), 1e-12f));
    }
}

// ======================= launch =======================
extern "C" void kernel_launch(void* const* d_in, const int* in_sizes, int n_in,
                              void* d_out, int out_size)
{
    const float* x = nullptr;
    const float* w1 = nullptr; const float* w2 = nullptr; const float* w3 = nullptr;
    const float* fcw = nullptr; const float* protos = nullptr;
    const float* bn64[4]  = {nullptr, nullptr, nullptr, nullptr};
    const float* bn128[4] = {nullptr, nullptr, nullptr, nullptr};
    const float* bn256[4] = {nullptr, nullptr, nullptr, nullptr};
    int c64 = 0, c128 = 0, c256 = 0;

    for (int i = 0; i < n_in; i++) {
        const float* p = (const float*)d_in[i];
        switch (in_sizes[i]) {
            case 3145728: x = p; break;
            case 1728:    w1 = p; break;
            case 73728:   w2 = p; break;
            case 294912:  w3 = p; break;
            case 8388608: fcw = p; break;
            case 5120:    protos = p; break;
            case 64:  if (c64  < 4) bn64[c64++]   = p; break;
            case 128: if (c128 < 4) bn128[c128++] = p; break;
            case 256: if (c256 < 4) bn256[c256++] = p; break;
            default: break;
        }
    }
    if (!x || !w1 || !w2 || !w3 || !fcw || !protos) return;

    cudaFuncSetAttribute(conv2_hmma, cudaFuncAttributeMaxDynamicSharedMemorySize, SMEM_BYTES);
    cudaFuncSetAttribute(conv3_hmma, cudaFuncAttributeMaxDynamicSharedMemorySize, SMEM_BYTES);

    wprep2<<<288, 256>>>(w2);
    wprep3<<<1152, 256>>>(w3);
    conv1_bn<<<dim3(4, 8, NIMG), 256>>>(x, w1, bn64[0], bn64[1], bn64[2], bn64[3]);
    lif1_kernel<<<32768, 256>>>();
    conv2_hmma<<<dim3(8, NIMG), 256, SMEM_BYTES>>>(bn128[0], bn128[1], bn128[2], bn128[3]);
    lif2_pool<<<16384, 256>>>();
    conv3_hmma<<<dim3(4, NIMG), 256, SMEM_BYTES>>>(bn256[0], bn256[1], bn256[2], bn256[3]);
    lif3_pool<<<8192, 256>>>();
    fc_gemm<<<dim3(8, 16), 256>>>(fcw);
    lif_fc_mean<<<256, 256>>>();
    final_head<<<BATCH, 256>>>(protos, (float*)d_out);
}

// round 16
// speedup vs baseline: 1.0057x; 1.0004x over previous
#include <cuda_runtime.h>
#include <cuda_bf16.h>
#include <cstdint>

#define T_STEPS 8
#define BATCH   128
#define NIMG    (T_STEPS * BATCH)   // 1024

// ======================= helpers =======================
__device__ __forceinline__ uint32_t smem_u32(const void* p) {
    uint32_t a;
    asm("{ .reg .u64 t; cvta.to.shared.u64 t, %1; cvt.u32.u64 %0, t; }" : "=r"(a) : "l"(p));
    return a;
}
#define SWZ(off) ((off) ^ (((off) >> 3) & 0x70))

#define MMA_BF16(acc, a, b0, b1) \
    asm volatile("mma.sync.aligned.m16n8k16.row.col.f32.bf16.bf16.f32 " \
        "{%0,%1,%2,%3}, {%4,%5,%6,%7}, {%8,%9}, {%0,%1,%2,%3};" \
        : "+f"((acc)[0]), "+f"((acc)[1]), "+f"((acc)[2]), "+f"((acc)[3]) \
        : "r"((a)[0]), "r"((a)[1]), "r"((a)[2]), "r"((a)[3]), "r"(b0), "r"(b1))

#define LDMATRIX_X4(a, addr) \
    asm volatile("ldmatrix.sync.aligned.m8n8.x4.shared.b16 {%0,%1,%2,%3}, [%4];" \
        : "=r"((a)[0]), "=r"((a)[1]), "=r"((a)[2]), "=r"((a)[3]) : "r"(addr))

// ======================= scratch =======================
__device__ __align__(16) float         g_pre1[NIMG * 1024 * 64];          // conv1 out [n][px][64c]
__device__ __align__(16) __nv_bfloat16 g_s1  [NIMG * 1024 * 64];          // spikes bf16
__device__ __align__(16) float         g_pre2[(size_t)NIMG * 1024 * 128]; // conv2 out [n][px][128c]
__device__ __align__(16) __nv_bfloat16 g_s2  [NIMG * 256 * 128];          // pooled spikes bf16
__device__ __align__(16) float         g_pre3[NIMG * 256 * 256];          // conv3 out [n][px][256c]
__device__ __align__(16) float         g_s3  [NIMG * 16384];              // fc input fp32 [n][c*64+h*8+w]
__device__ __align__(16) __nv_bfloat16 g_w2s [3 * 9 * 128 * 64];          // [s][kk][co][cin]
__device__ __align__(16) __nv_bfloat16 g_w3s [3 * 9 * 2 * 2 * 128 * 64];  // [s][kk][cc][nt][co][cin]
__device__ float g_fc  [NIMG * 512];
__device__ float g_feat[BATCH * 512];

// smem layout (bytes): BN at 16 (3*512), A slab at 2048 (16KB, SW128),
// B slabs at 18432 (3 x 18432, rows padded to 144B)
#define SM_BN    16
#define SM_A     2048
#define SM_B     18432
#define SM_BSLAB 18432
#define SMEM_BYTES 73728

// ======================= weight splitting (exact 8+8+8) =======================
__device__ __forceinline__ void split3(float w, __nv_bfloat16& h, __nv_bfloat16& m, __nv_bfloat16& l)
{
    h = __float2bfloat16_rz(w);
    float r1 = w - __bfloat162float(h);
    m = __float2bfloat16_rz(r1);
    float r2 = r1 - __bfloat162float(m);
    l = __float2bfloat16_rz(r2);
}

__global__ void wprep2(const float* __restrict__ w2)
{
    int i = blockIdx.x * 256 + threadIdx.x;          // 128*64*9 = 73728
    if (i >= 128 * 64 * 9) return;
    int co = i / 576, r = i % 576, cin = r / 9, kk = r % 9;
    __nv_bfloat16 h, m, l;
    split3(w2[co * 576 + cin * 9 + kk], h, m, l);
    int base = kk * 8192 + co * 64 + cin;
    g_w2s[base] = h; g_w2s[9 * 8192 + base] = m; g_w2s[18 * 8192 + base] = l;
}

__global__ void wprep3(const float* __restrict__ w3)
{
    int i = blockIdx.x * 256 + threadIdx.x;          // 256*128*9 = 294912
    if (i >= 256 * 128 * 9) return;
    int co = i / 1152, r = i % 1152, cin = r / 9, kk = r % 9;
    __nv_bfloat16 h, m, l;
    split3(w3[co * 1152 + cin * 9 + kk], h, m, l);
    int nt = co >> 7, col = co & 127, cc = cin >> 6, cinl = cin & 63;
    int idx = ((((kk * 2 + cc) * 2 + nt) * 128 + col) * 64 + cinl);
    g_w3s[idx] = h;
    g_w3s[294912 + idx] = m;
    g_w3s[2 * 294912 + idx] = l;
}

// ======================= conv1: 3->64, scalar, out [n][px][c] =======================
__global__ void __launch_bounds__(256) conv1_bn(
    const float* __restrict__ x, const float* __restrict__ w,
    const float* __restrict__ g, const float* __restrict__ bb,
    const float* __restrict__ mm, const float* __restrict__ vv)
{
    const int n   = blockIdx.z;
    const int co0 = blockIdx.y * 8;
    const int pix = blockIdx.x * 256 + threadIdx.x;
    const int h = pix >> 5, wi = pix & 31;

    __shared__ float ws[8 * 27];
    if (threadIdx.x < 216) ws[threadIdx.x] = w[co0 * 27 + threadIdx.x];
    __syncthreads();

    const float* xb = x + n * 3 * 1024;
    float acc[8];
#pragma unroll
    for (int j = 0; j < 8; j++) acc[j] = 0.f;

#pragma unroll
    for (int c = 0; c < 3; c++)
#pragma unroll
        for (int ky = 0; ky < 3; ky++)
#pragma unroll
            for (int kx = 0; kx < 3; kx++) {
                int ih = h + ky - 1, iw = wi + kx - 1;
                float v = 0.f;
                if ((unsigned)ih < 32u && (unsigned)iw < 32u)
                    v = __ldg(&xb[c * 1024 + ih * 32 + iw]);
                int k = c * 9 + ky * 3 + kx;
#pragma unroll
                for (int j = 0; j < 8; j++)
                    acc[j] = fmaf(v, ws[j * 27 + k], acc[j]);
            }

#pragma unroll
    for (int j = 0; j < 8; j++) {
        int c = co0 + j;
        float scale = g[c] * rsqrtf(vv[c] + 1e-5f);
        g_pre1[((size_t)n * 1024 + pix) * 64 + c] = (acc[j] - mm[c]) * scale + bb[c];
    }
}

// ======================= lif1: pre1 -> bf16 spikes =======================
__global__ void lif1_kernel()
{
    const size_t i = (size_t)blockIdx.x * 256 + threadIdx.x;   // B*1024*64
    const size_t stride = (size_t)BATCH * 1024 * 64;
    float v = 0.f;
#pragma unroll
    for (int t = 0; t < T_STEPS; t++) {
        float xv = g_pre1[t * stride + i];
        v = v + (xv - v) * 0.5f;
        float s = (v >= 1.0f) ? 1.0f : 0.0f;
        g_s1[t * stride + i] = __float2bfloat16(s);
        v = v * (1.0f - s);
    }
}

// ======================= conv2: 64->128, HMMA implicit GEMM =======================
// grid (8 m-tiles, 1024 imgs), block 256 (8 warps = 2m x 4n).
__global__ void __launch_bounds__(256, 2) conv2_hmma(
    const float* __restrict__ g, const float* __restrict__ bb,
    const float* __restrict__ mm, const float* __restrict__ vv)
{
    extern __shared__ char smem[];
    const int n     = blockIdx.y;
    const int mbase = blockIdx.x * 128;
    const int tid   = threadIdx.x;
    const int lane  = tid & 31, warp = tid >> 5;
    const int wm = warp >> 2, wn = warp & 3;
    const uint32_t smb = smem_u32(smem);

    float* s_scl = (float*)(smem + SM_BN);
    float* s_nm  = (float*)(smem + SM_BN + 512);
    float* s_bi  = (float*)(smem + SM_BN + 1024);
    if (tid < 128) {
        float sc = g[tid] * rsqrtf(vv[tid] + 1e-5f);
        s_scl[tid] = sc; s_nm[tid] = -mm[tid]; s_bi[tid] = bb[tid];
    }

    float acc[4][4][4];
#pragma unroll
    for (int a = 0; a < 4; a++)
#pragma unroll
        for (int b = 0; b < 4; b++)
#pragma unroll
            for (int c = 0; c < 4; c++) acc[a][b][c] = 0.f;

    const int row = tid >> 1, half = tid & 1;
    const uint4 z4 = make_uint4(0, 0, 0, 0);

#pragma unroll 1
    for (int kk = 0; kk < 9; kk++) {
        const int ky = kk / 3 - 1, kx = kk % 3 - 1;
        __syncthreads();
        // A slab: 128 px x 64 cin bf16, SW128 swizzle, zero-padded at borders
        {
            int px = mbase + row;
            int h = (px >> 5) + ky, w = (px & 31) + kx;
            bool ok = (unsigned)h < 32u && (unsigned)w < 32u;
            const uint4* src = (const uint4*)(g_s1 + ((size_t)(n * 1024 + h * 32 + w) * 64 + half * 32));
#pragma unroll
            for (int j = 0; j < 4; j++) {
                uint4 v = ok ? __ldg(src + j) : z4;
                *(uint4*)(smem + SM_A + SWZ(row * 128 + half * 64 + j * 16)) = v;
            }
        }
        // B slabs: 3 splits x 128 co x 64 cin, rows padded to 144B
#pragma unroll 1
        for (int it = tid; it < 3 * 128 * 8; it += 256) {
            int s = it >> 10, r = it & 1023, co = r >> 3, q = r & 7;
            const uint4* src = (const uint4*)(g_w2s + ((size_t)(s * 9 + kk) * 128 + co) * 64 + q * 8);
            *(uint4*)(smem + SM_B + s * SM_BSLAB + co * 144 + q * 16) = __ldg(src);
        }
        __syncthreads();

#pragma unroll
        for (int ks = 0; ks < 4; ks++) {
            uint32_t afr[4][4];
#pragma unroll
            for (int mi = 0; mi < 4; mi++) {
                int arow = wm * 64 + mi * 16 + (lane & 7) + ((lane >> 3) & 1) * 8;
                int acol = ks * 32 + ((lane >> 4) & 1) * 16;
                uint32_t addr = smb + SM_A + SWZ(arow * 128 + acol);
                LDMATRIX_X4(afr[mi], addr);
            }
#pragma unroll
            for (int s = 0; s < 3; s++) {
#pragma unroll
                for (int nj = 0; nj < 4; nj++) {
                    int nn = wn * 32 + nj * 8 + (lane >> 2);
                    int k0 = ks * 16 + (lane & 3) * 2;
                    const char* bp = smem + SM_B + s * SM_BSLAB + nn * 144 + k0 * 2;
                    uint32_t b0 = *(const uint32_t*)bp;
                    uint32_t b1 = *(const uint32_t*)(bp + 16);
#pragma unroll
                    for (int mi = 0; mi < 4; mi++)
                        MMA_BF16(acc[mi][nj], afr[mi], b0, b1);
                }
            }
        }
    }

    // epilogue: BN, write [n][px][128]
    float* obase = g_pre2 + (size_t)n * 1024 * 128;
#pragma unroll
    for (int mi = 0; mi < 4; mi++) {
        int px0 = mbase + wm * 64 + mi * 16 + (lane >> 2);
#pragma unroll
        for (int nj = 0; nj < 4; nj++) {
            int co = wn * 32 + nj * 8 + (lane & 3) * 2;
            float sc0 = s_scl[co], sc1 = s_scl[co + 1];
            float nm0 = s_nm[co],  nm1 = s_nm[co + 1];
            float bi0 = s_bi[co],  bi1 = s_bi[co + 1];
            float2 v0 = make_float2(fmaf(acc[mi][nj][0] + nm0, sc0, bi0),
                                    fmaf(acc[mi][nj][1] + nm1, sc1, bi1));
            float2 v1 = make_float2(fmaf(acc[mi][nj][2] + nm0, sc0, bi0),
                                    fmaf(acc[mi][nj][3] + nm1, sc1, bi1));
            *(float2*)(obase + (size_t)px0 * 128 + co)       = v0;
            *(float2*)(obase + (size_t)(px0 + 8) * 128 + co) = v1;
        }
    }
}

// ======================= conv3: 128->256, HMMA implicit GEMM =======================
// grid (4 = 2mt x 2nt, 1024 imgs), block 256. 18 chunks (kk x cinchunk).
__global__ void __launch_bounds__(256, 2) conv3_hmma(
    const float* __restrict__ g, const float* __restrict__ bb,
    const float* __restrict__ mm, const float* __restrict__ vv)
{
    extern __shared__ char smem[];
    const int n  = blockIdx.y;
    const int mt = blockIdx.x >> 1, nt = blockIdx.x & 1;
    const int tid  = threadIdx.x;
    const int lane = tid & 31, warp = tid >> 5;
    const int wm = warp >> 2, wn = warp & 3;
    const uint32_t smb = smem_u32(smem);

    float* s_scl = (float*)(smem + SM_BN);
    float* s_nm  = (float*)(smem + SM_BN + 512);
    float* s_bi  = (float*)(smem + SM_BN + 1024);
    if (tid < 128) {
        int c = nt * 128 + tid;
        float sc = g[c] * rsqrtf(vv[c] + 1e-5f);
        s_scl[tid] = sc; s_nm[tid] = -mm[c]; s_bi[tid] = bb[c];
    }

    float acc[4][4][4];
#pragma unroll
    for (int a = 0; a < 4; a++)
#pragma unroll
        for (int b = 0; b < 4; b++)
#pragma unroll
            for (int c = 0; c < 4; c++) acc[a][b][c] = 0.f;

    const int row = tid >> 1, half = tid & 1;
    const uint4 z4 = make_uint4(0, 0, 0, 0);

#pragma unroll 1
    for (int ch = 0; ch < 18; ch++) {
        const int kk = ch >> 1, cc = ch & 1;
        const int ky = kk / 3 - 1, kx = kk % 3 - 1;
        __syncthreads();
        // A slab from g_s2 [n][256px][128cin], take cin chunk cc
        {
            int px = mt * 128 + row;
            int h = (px >> 4) + ky, w = (px & 15) + kx;
            bool ok = (unsigned)h < 16u && (unsigned)w < 16u;
            const uint4* src = (const uint4*)(g_s2 + ((size_t)(n * 256 + h * 16 + w) * 128 + cc * 64 + half * 32));
#pragma unroll
            for (int j = 0; j < 4; j++) {
                uint4 v = ok ? __ldg(src + j) : z4;
                *(uint4*)(smem + SM_A + SWZ(row * 128 + half * 64 + j * 16)) = v;
            }
        }
        // B slabs: [s][kk][cc][nt][co][cin]
#pragma unroll 1
        for (int it = tid; it < 3 * 128 * 8; it += 256) {
            int s = it >> 10, r = it & 1023, co = r >> 3, q = r & 7;
            size_t bidx = (size_t)s * 294912 + ((size_t)(((kk * 2 + cc) * 2 + nt) * 128 + co)) * 64 + q * 8;
            *(uint4*)(smem + SM_B + s * SM_BSLAB + co * 144 + q * 16) = __ldg((const uint4*)(g_w3s + bidx));
        }
        __syncthreads();

#pragma unroll
        for (int ks = 0; ks < 4; ks++) {
            uint32_t afr[4][4];
#pragma unroll
            for (int mi = 0; mi < 4; mi++) {
                int arow = wm * 64 + mi * 16 + (lane & 7) + ((lane >> 3) & 1) * 8;
                int acol = ks * 32 + ((lane >> 4) & 1) * 16;
                uint32_t addr = smb + SM_A + SWZ(arow * 128 + acol);
                LDMATRIX_X4(afr[mi], addr);
            }
#pragma unroll
            for (int s = 0; s < 3; s++) {
#pragma unroll
                for (int nj = 0; nj < 4; nj++) {
                    int nn = wn * 32 + nj * 8 + (lane >> 2);
                    int k0 = ks * 16 + (lane & 3) * 2;
                    const char* bp = smem + SM_B + s * SM_BSLAB + nn * 144 + k0 * 2;
                    uint32_t b0 = *(const uint32_t*)bp;
                    uint32_t b1 = *(const uint32_t*)(bp + 16);
#pragma unroll
                    for (int mi = 0; mi < 4; mi++)
                        MMA_BF16(acc[mi][nj], afr[mi], b0, b1);
                }
            }
        }
    }

    // epilogue: BN, write [n][px][256] (cols nt*128..+128)
    float* obase = g_pre3 + (size_t)n * 256 * 256 + nt * 128;
#pragma unroll
    for (int mi = 0; mi < 4; mi++) {
        int px0 = mt * 128 + wm * 64 + mi * 16 + (lane >> 2);
#pragma unroll
        for (int nj = 0; nj < 4; nj++) {
            int co = wn * 32 + nj * 8 + (lane & 3) * 2;
            float sc0 = s_scl[co], sc1 = s_scl[co + 1];
            float nm0 = s_nm[co],  nm1 = s_nm[co + 1];
            float bi0 = s_bi[co],  bi1 = s_bi[co + 1];
            float2 v0 = make_float2(fmaf(acc[mi][nj][0] + nm0, sc0, bi0),
                                    fmaf(acc[mi][nj][1] + nm1, sc1, bi1));
            float2 v1 = make_float2(fmaf(acc[mi][nj][2] + nm0, sc0, bi0),
                                    fmaf(acc[mi][nj][3] + nm1, sc1, bi1));
            *(float2*)(obase + (size_t)px0 * 256 + co)       = v0;
            *(float2*)(obase + (size_t)(px0 + 8) * 256 + co) = v1;
        }
    }
}

// ======================= lif2 + pool: pre2 -> s2 bf16 =======================
__global__ void lif2_pool()
{
    const int i = blockIdx.x * 256 + threadIdx.x;   // B*16*16*128
    const int co = i & 127;
    const int wo = (i >> 7) & 15;
    const int ho = (i >> 11) & 15;
    const int b  = i >> 15;

    float v00 = 0.f, v01 = 0.f, v10 = 0.f, v11 = 0.f;
#pragma unroll
    for (int t = 0; t < T_STEPS; t++) {
        const float* p = g_pre2 + ((size_t)((t * BATCH + b) * 1024 + (2 * ho) * 32 + 2 * wo)) * 128 + co;
        float x00 = p[0], x01 = p[128], x10 = p[32 * 128], x11 = p[33 * 128];
        v00 += (x00 - v00) * 0.5f; float s00 = (v00 >= 1.f) ? 1.f : 0.f; v00 *= (1.f - s00);
        v01 += (x01 - v01) * 0.5f; float s01 = (v01 >= 1.f) ? 1.f : 0.f; v01 *= (1.f - s01);
        v10 += (x10 - v10) * 0.5f; float s10 = (v10 >= 1.f) ? 1.f : 0.f; v10 *= (1.f - s10);
        v11 += (x11 - v11) * 0.5f; float s11 = (v11 >= 1.f) ? 1.f : 0.f; v11 *= (1.f - s11);
        float s = fmaxf(fmaxf(s00, s01), fmaxf(s10, s11));
        g_s2[((size_t)(t * BATCH + b) * 256 + ho * 16 + wo) * 128 + co] = __float2bfloat16(s);
    }
}

// ======================= lif3 + pool: pre3 -> s3 fp32 (c*64+h*8+w order) =======================
__global__ void lif3_pool()
{
    const int i = blockIdx.x * 256 + threadIdx.x;   // B*8*8*256
    const int co = i & 255;
    const int wo = (i >> 8) & 7;
    const int ho = (i >> 11) & 7;
    const int b  = i >> 14;

    float v00 = 0.f, v01 = 0.f, v10 = 0.f, v11 = 0.f;
#pragma unroll
    for (int t = 0; t < T_STEPS; t++) {
        const float* p = g_pre3 + ((size_t)((t * BATCH + b) * 256 + (2 * ho) * 16 + 2 * wo)) * 256 + co;
        float x00 = p[0], x01 = p[256], x10 = p[16 * 256], x11 = p[17 * 256];
        v00 += (x00 - v00) * 0.5f; float s00 = (v00 >= 1.f) ? 1.f : 0.f; v00 *= (1.f - s00);
        v01 += (x01 - v01) * 0.5f; float s01 = (v01 >= 1.f) ? 1.f : 0.f; v01 *= (1.f - s01);
        v10 += (x10 - v10) * 0.5f; float s10 = (v10 >= 1.f) ? 1.f : 0.f; v10 *= (1.f - s10);
        v11 += (x11 - v11) * 0.5f; float s11 = (v11 >= 1.f) ? 1.f : 0.f; v11 *= (1.f - s11);
        float s = fmaxf(fmaxf(s00, s01), fmaxf(s10, s11));
        g_s3[(size_t)(t * BATCH + b) * 16384 + co * 64 + ho * 8 + wo] = s;
    }
}

// ======================= FC GEMM =======================
__global__ void __launch_bounds__(256) fc_gemm(const float* __restrict__ W)
{
    const int f0 = blockIdx.x * 64;
    const int m0 = blockIdx.y * 64;
    const int tid = threadIdx.x;
    const int tx = tid & 15, ty = tid >> 4;

    __shared__ float As[16][64];
    __shared__ float Bs[16][64];

    float acc[4][4];
#pragma unroll
    for (int i = 0; i < 4; i++)
#pragma unroll
        for (int j = 0; j < 4; j++) acc[i][j] = 0.f;

    const int lrow = tid >> 2;
    const int lk   = (tid & 3) * 4;

    for (int k0 = 0; k0 < 16384; k0 += 16) {
        float4 a = *(const float4*)(g_s3 + (size_t)(m0 + lrow) * 16384 + k0 + lk);
        float4 b = *(const float4*)(W + (size_t)(f0 + lrow) * 16384 + k0 + lk);
        As[lk + 0][lrow] = a.x; As[lk + 1][lrow] = a.y;
        As[lk + 2][lrow] = a.z; As[lk + 3][lrow] = a.w;
        Bs[lk + 0][lrow] = b.x; Bs[lk + 1][lrow] = b.y;
        Bs[lk + 2][lrow] = b.z; Bs[lk + 3][lrow] = b.w;
        __syncthreads();
#pragma unroll
        for (int kk = 0; kk < 16; kk++) {
            float4 ra = *(const float4*)&As[kk][ty * 4];
            float4 rb = *(const float4*)&Bs[kk][tx * 4];
            float av[4] = {ra.x, ra.y, ra.z, ra.w};
            float bv[4] = {rb.x, rb.y, rb.z, rb.w};
#pragma unroll
            for (int i = 0; i < 4; i++)
#pragma unroll
                for (int j = 0; j < 4; j++)
                    acc[i][j] = fmaf(av[i], bv[j], acc[i][j]);
        }
        __syncthreads();
    }

#pragma unroll
    for (int i = 0; i < 4; i++)
#pragma unroll
        for (int j = 0; j < 4; j++)
            g_fc[(m0 + ty * 4 + i) * 512 + f0 + tx * 4 + j] = acc[i][j];
}

// ======================= LIF fc + mean =======================
__global__ void lif_fc_mean()
{
    const int i = blockIdx.x * 256 + threadIdx.x;
    float v = 0.f, sum = 0.f;
#pragma unroll
    for (int t = 0; t < T_STEPS; t++) {
        float xv = g_fc[t * (BATCH * 512) + i];
        v = v + (xv - v) * 0.5f;
        float s = (v >= 1.0f) ? 1.0f : 0.0f;
        v = v * (1.0f - s);
        sum += s;
    }
    g_feat[i] = sum * 0.125f;
}

// ======================= cosine head =======================
__device__ __forceinline__ float blk_sum(float v, float* red)
{
    const int lane = threadIdx.x & 31, wp = threadIdx.x >> 5;
#pragma unroll
    for (int o = 16; o > 0; o >>= 1) v += __shfl_down_sync(0xffffffffu, v, o);
    if (lane == 0) red[wp] = v;
    __syncthreads();
    float r = (threadIdx.x < 8) ? red[threadIdx.x] : 0.f;
    if (wp == 0) {
#pragma unroll
        for (int o = 4; o > 0; o >>= 1) r += __shfl_down_sync(0xffu, r, o);
        if (lane == 0) red[0] = r;
    }
    __syncthreads();
    float res = red[0];
    __syncthreads();
    return res;
}

__global__ void final_head(const float* __restrict__ protos, float* __restrict__ out)
{
    const int b = blockIdx.x;
    const int tid = threadIdx.x;
    __shared__ float sf[512];
    __shared__ float red[8];

    for (int i = tid; i < 512; i += 256) sf[i] = g_feat[b * 512 + i];
    __syncthreads();

    float ps = 0.f;
    for (int i = tid; i < 512; i += 256) ps += sf[i] * sf[i];
    float nf = sqrtf(blk_sum(ps, red));
    nf = fmaxf(nf, 1e-12f);

    for (int p = 0; p < 10; p++) {
        float pd = 0.f, pq = 0.f;
        for (int i = tid; i < 512; i += 256) {
            float pv = __ldg(&protos[p * 512 + i]);
            pd += sf[i] * pv;
            pq += pv * pv;
        }
        pd = blk_sum(pd, red);
        pq = blk_sum(pq, red);
        if (tid == 0)
            out[b * 10 + p] = 10.f * pd / (nf * fmaxf(sqrtf(pq), 1e-12f));
    }
}

// ======================= launch =======================
extern "C" void kernel_launch(void* const* d_in, const int* in_sizes, int n_in,
                              void* d_out, int out_size)
{
    const float* x = nullptr;
    const float* w1 = nullptr; const float* w2 = nullptr; const float* w3 = nullptr;
    const float* fcw = nullptr; const float* protos = nullptr;
    const float* bn64[4]  = {nullptr, nullptr, nullptr, nullptr};
    const float* bn128[4] = {nullptr, nullptr, nullptr, nullptr};
    const float* bn256[4] = {nullptr, nullptr, nullptr, nullptr};
    int c64 = 0, c128 = 0, c256 = 0;

    for (int i = 0; i < n_in; i++) {
        const float* p = (const float*)d_in[i];
        switch (in_sizes[i]) {
            case 3145728: x = p; break;
            case 1728:    w1 = p; break;
            case 73728:   w2 = p; break;
            case 294912:  w3 = p; break;
            case 8388608: fcw = p; break;
            case 5120:    protos = p; break;
            case 64:  if (c64  < 4) bn64[c64++]   = p; break;
            case 128: if (c128 < 4) bn128[c128++] = p; break;
            case 256: if (c256 < 4) bn256[c256++] = p; break;
            default: break;
        }
    }
    if (!x || !w1 || !w2 || !w3 || !fcw || !protos) return;

    cudaFuncSetAttribute(conv2_hmma, cudaFuncAttributeMaxDynamicSharedMemorySize, SMEM_BYTES);
    cudaFuncSetAttribute(conv3_hmma, cudaFuncAttributeMaxDynamicSharedMemorySize, SMEM_BYTES);

    wprep2<<<288, 256>>>(w2);
    wprep3<<<1152, 256>>>(w3);
    conv1_bn<<<dim3(4, 8, NIMG), 256>>>(x, w1, bn64[0], bn64[1], bn64[2], bn64[3]);
    lif1_kernel<<<32768, 256>>>();
    conv2_hmma<<<dim3(8, NIMG), 256, SMEM_BYTES>>>(bn128[0], bn128[1], bn128[2], bn128[3]);
    lif2_pool<<<16384, 256>>>();
    conv3_hmma<<<dim3(4, NIMG), 256, SMEM_BYTES>>>(bn256[0], bn256[1], bn256[2], bn256[3]);
    lif3_pool<<<8192, 256>>>();
    fc_gemm<<<dim3(8, 16), 256>>>(fcw);
    lif_fc_mean<<<256, 256>>>();
    final_head<<<BATCH, 256>>>(protos, (float*)d_out);
}